// round 1
// baseline (speedup 1.0000x reference)
#include <cuda_runtime.h>
#include <cuda_bf16.h>
#include <math.h>

// ---------------- problem constants ----------------
#define BATCH 32
#define CH    256
#define HH    56
#define WW    56
#define HWS   (HH*WW)          // 3136
#define TOK   (BATCH*HWS)      // 100352
#define WS7   7
#define SHIFT3 3
#define HEADS 8
#define HDIM  32
#define HIDDEN 1024
#define QKVN  768

// ---------------- scratch (device globals; no allocation allowed) ----------------
__device__ float g_ywin [(size_t)TOK*CH];     // LN1 output, window-token order
__device__ float g_xbhwc[(size_t)TOK*CH];     // shortcut, (b,h,w,c)
__device__ float g_qkv  [(size_t)TOK*QKVN];   // qkv, window-token order
__device__ float g_ow   [(size_t)TOK*CH];     // attention out, window-token order
__device__ float g_x1   [(size_t)TOK*CH];     // shortcut + proj out, (b,h,w,c)
__device__ float g_h2   [(size_t)TOK*CH];     // LN2 out
__device__ float g_hmid [(size_t)TOK*HIDDEN]; // mlp hidden
__device__ float g_x2   [(size_t)TOK*CH];     // final (b,h,w,c)

// ---------------- kernel 1: LN1 + shift + window partition + NHWC shortcut ----------------
// block = one batch element x 32 spatial positions. smem tile [256ch][32hw].
__global__ __launch_bounds__(256) void ln1_kernel(
    const float* __restrict__ x, const float* __restrict__ g, const float* __restrict__ bta,
    float* __restrict__ ywin, float* __restrict__ xbhwc)
{
    __shared__ float ts[256*33];
    __shared__ float cmu[32], crs[32];
    const int blk = blockIdx.x;
    const int b   = blk / 98;
    const int hw0 = (blk % 98) * 32;
    const int tid = threadIdx.x;
    const float* xb = x + (size_t)b*CH*HWS;

    // coalesced load: each warp reads 32 consecutive hw for one channel
    for (int idx = tid; idx < 256*32; idx += 256) {
        int ch = idx >> 5, j = idx & 31;
        ts[ch*33 + j] = xb[(size_t)ch*HWS + hw0 + j];
    }
    __syncthreads();

    // per-column (token) mean/var: 32 cols x 8 threads
    {
        int col = tid >> 3, kk = tid & 7;
        float s = 0.f, s2 = 0.f;
        for (int ch = kk; ch < 256; ch += 8) {
            float v = ts[ch*33 + col];
            s += v; s2 += v*v;
        }
        #pragma unroll
        for (int o = 4; o; o >>= 1) {
            s  += __shfl_down_sync(0xffffffffu, s,  o, 8);
            s2 += __shfl_down_sync(0xffffffffu, s2, o, 8);
        }
        if (kk == 0) {
            float mu = s * (1.f/256.f);
            cmu[col] = mu;
            crs[col] = rsqrtf(s2*(1.f/256.f) - mu*mu + 1e-5f);
        }
    }
    __syncthreads();

    const float gg = g[tid], bb = bta[tid];
    for (int j = 0; j < 32; j++) {
        int hw = hw0 + j;
        int h = hw / 56, w = hw % 56;
        int hs = h + (56 - SHIFT3); if (hs >= 56) hs -= 56;   // (h - 3) mod 56
        int wsh = w + (56 - SHIFT3); if (wsh >= 56) wsh -= 56;
        int wi = hs / 7, r = hs % 7;
        int wj = wsh / 7, c = wsh % 7;
        int win = ((b << 3) + wi) * 8 + wj;
        int n = r*7 + c;
        float v = ts[tid*33 + j];
        xbhwc[((size_t)b*HWS + hw)*CH + tid] = v;
        ywin [((size_t)win*49 + n)*CH + tid] = (v - cmu[j]) * crs[j] * gg + bb;
    }
}

// ---------------- generic fp32 SGEMM 128x128x16, 8x8/thread ----------------
#define BM 128
#define BN 128
#define BK 16
#define TM 8
#define TN 8

enum { EPI_BIAS = 0, EPI_PROJ = 1, EPI_GELU = 2, EPI_RES = 3 };

template<int EPI>
__global__ __launch_bounds__(256) void sgemm_k(
    const float* __restrict__ A, const float* __restrict__ B,
    const float* __restrict__ bias, float* __restrict__ C,
    const float* __restrict__ aux,
    int M, int N, int K)
{
    __shared__ float As[BK][BM];
    __shared__ float Bs[BK][BN];
    const int tid = threadIdx.x;
    const int tx = tid & 15, ty = tid >> 4;
    const int m0 = blockIdx.y * BM, n0 = blockIdx.x * BN;

    float acc[TM][TN];
    #pragma unroll
    for (int i = 0; i < TM; i++)
        #pragma unroll
        for (int j = 0; j < TN; j++) acc[i][j] = 0.f;

    const int arow0 = tid >> 2;          // 0..63
    const int acol0 = (tid & 3) * 4;     // 0,4,8,12
    const int brow0 = tid >> 5;          // 0..7
    const int bcol0 = (tid & 31) * 4;    // 0..124

    for (int k0 = 0; k0 < K; k0 += BK) {
        #pragma unroll
        for (int h = 0; h < 2; h++) {
            int r = arow0 + h*64;
            float4 va = *reinterpret_cast<const float4*>(&A[(size_t)(m0 + r)*K + k0 + acol0]);
            As[acol0+0][r] = va.x; As[acol0+1][r] = va.y;
            As[acol0+2][r] = va.z; As[acol0+3][r] = va.w;
        }
        #pragma unroll
        for (int h = 0; h < 2; h++) {
            int r = brow0 + h*8;
            float4 vb = *reinterpret_cast<const float4*>(&B[(size_t)(k0 + r)*N + n0 + bcol0]);
            *reinterpret_cast<float4*>(&Bs[r][bcol0]) = vb;
        }
        __syncthreads();
        #pragma unroll
        for (int kk = 0; kk < BK; kk++) {
            float a[TM], bfr[TN];
            #pragma unroll
            for (int i = 0; i < TM; i++) a[i]   = As[kk][ty*TM + i];
            #pragma unroll
            for (int j = 0; j < TN; j++) bfr[j] = Bs[kk][tx*TN + j];
            #pragma unroll
            for (int i = 0; i < TM; i++)
                #pragma unroll
                for (int j = 0; j < TN; j++)
                    acc[i][j] += a[i] * bfr[j];
        }
        __syncthreads();
    }

    // epilogue
    #pragma unroll
    for (int i = 0; i < TM; i++) {
        int m = m0 + ty*TM + i;
        int nc = n0 + tx*TN;
        if (EPI == EPI_BIAS) {
            #pragma unroll
            for (int j = 0; j < TN; j++)
                C[(size_t)m*N + nc + j] = acc[i][j] + bias[nc + j];
        } else if (EPI == EPI_PROJ) {
            // window-token row m -> spatial row, + shortcut
            int win = m / 49, n = m % 49;
            int bb = win >> 6;
            int wr = (win >> 3) & 7;
            int wc = win & 7;
            int r = n / 7, c = n % 7;
            int h = wr*7 + r + SHIFT3; if (h >= 56) h -= 56;
            int w = wc*7 + c + SHIFT3; if (w >= 56) w -= 56;
            size_t drow = (size_t)bb*HWS + h*56 + w;
            #pragma unroll
            for (int j = 0; j < TN; j++) {
                int col = nc + j;
                C[drow*CH + col] = acc[i][j] + bias[col] + aux[drow*CH + col];
            }
        } else if (EPI == EPI_GELU) {
            #pragma unroll
            for (int j = 0; j < TN; j++) {
                int col = nc + j;
                float v = acc[i][j] + bias[col];
                C[(size_t)m*N + col] = 0.5f * v * (1.f + erff(v * 0.70710678118654752f));
            }
        } else { // EPI_RES
            #pragma unroll
            for (int j = 0; j < TN; j++) {
                int col = nc + j;
                C[(size_t)m*N + col] = acc[i][j] + bias[col] + aux[(size_t)m*N + col];
            }
        }
    }
}

// ---------------- kernel 3: windowed attention, one block per (window, head) ----------------
__global__ __launch_bounds__(256) void attn_kernel(
    const float* __restrict__ qkv, float* __restrict__ o)
{
    __shared__ float qs[49*33], ks[49*33], vs[49*33];
    __shared__ float ps[49*49];
    const int win  = blockIdx.x >> 3;
    const int head = blockIdx.x & 7;
    const int tid  = threadIdx.x;
    const size_t base = (size_t)win*49*QKVN + head*HDIM;

    for (int idx = tid; idx < 49*32; idx += 256) {
        int n = idx >> 5, c = idx & 31;
        size_t rb = base + (size_t)n*QKVN;
        qs[n*33 + c] = qkv[rb + c];
        ks[n*33 + c] = qkv[rb + 256 + c];
        vs[n*33 + c] = qkv[rb + 512 + c];
    }
    __syncthreads();

    const float scale = 0.17677669529663687f; // 32^-0.5
    for (int s = tid; s < 49*49; s += 256) {
        int i = s / 49, j = s % 49;
        float sum = 0.f;
        #pragma unroll
        for (int c = 0; c < 32; c++) sum += qs[i*33 + c] * ks[j*33 + c];
        ps[s] = sum * scale;
    }
    __syncthreads();

    if (tid < 49) {
        float mx = -1e30f;
        #pragma unroll 7
        for (int j = 0; j < 49; j++) mx = fmaxf(mx, ps[tid*49 + j]);
        float sum = 0.f;
        #pragma unroll 7
        for (int j = 0; j < 49; j++) {
            float e = __expf(ps[tid*49 + j] - mx);
            ps[tid*49 + j] = e; sum += e;
        }
        float inv = 1.f / sum;
        #pragma unroll 7
        for (int j = 0; j < 49; j++) ps[tid*49 + j] *= inv;
    }
    __syncthreads();

    for (int idx = tid; idx < 49*32; idx += 256) {
        int i = idx >> 5, c = idx & 31;
        float sum = 0.f;
        #pragma unroll 7
        for (int j = 0; j < 49; j++) sum += ps[i*49 + j] * vs[j*33 + c];
        o[((size_t)win*49 + i)*CH + head*HDIM + c] = sum;
    }
}

// ---------------- kernel 5: LN2, one block per token (rows contiguous) ----------------
__global__ __launch_bounds__(256) void ln2_kernel(
    const float* __restrict__ x, const float* __restrict__ g, const float* __restrict__ bta,
    float* __restrict__ y)
{
    const int row = blockIdx.x;
    const int tid = threadIdx.x;
    float v = x[(size_t)row*CH + tid];
    float s = v, s2 = v*v;
    #pragma unroll
    for (int o = 16; o; o >>= 1) {
        s  += __shfl_down_sync(0xffffffffu, s,  o);
        s2 += __shfl_down_sync(0xffffffffu, s2, o);
    }
    __shared__ float ws[8], ws2[8];
    int wid = tid >> 5, lane = tid & 31;
    if (lane == 0) { ws[wid] = s; ws2[wid] = s2; }
    __syncthreads();
    if (tid == 0) {
        float ts = 0.f, ts2 = 0.f;
        #pragma unroll
        for (int i = 0; i < 8; i++) { ts += ws[i]; ts2 += ws2[i]; }
        float mu = ts * (1.f/256.f);
        ws[0] = mu;
        ws2[0] = rsqrtf(ts2*(1.f/256.f) - mu*mu + 1e-5f);
    }
    __syncthreads();
    float mu = ws[0], rstd = ws2[0];
    y[(size_t)row*CH + tid] = (v - mu) * rstd * g[tid] + bta[tid];
}

// ---------------- kernel 8: (b,hw,c) -> (b,c,hw) ----------------
__global__ __launch_bounds__(256) void transpose_out(
    const float* __restrict__ x2, float* __restrict__ out)
{
    __shared__ float t[32][33];
    const int b   = blockIdx.z;
    const int c0  = blockIdx.y * 32;
    const int hw0 = blockIdx.x * 32;
    const int j = threadIdx.x & 31;
    const int i = threadIdx.x >> 5;
    for (int ii = i; ii < 32; ii += 8)
        t[ii][j] = x2[((size_t)b*HWS + hw0 + ii)*CH + c0 + j];
    __syncthreads();
    for (int ii = i; ii < 32; ii += 8)
        out[((size_t)(b*CH + c0 + ii))*HWS + hw0 + j] = t[j][ii];
}

// ---------------- launch ----------------
extern "C" void kernel_launch(void* const* d_in, const int* in_sizes, int n_in,
                              void* d_out, int out_size)
{
    const float* x      = (const float*)d_in[0];
    const float* n1_g   = (const float*)d_in[1];
    const float* n1_b   = (const float*)d_in[2];
    const float* qkv_w  = (const float*)d_in[3];
    const float* qkv_b  = (const float*)d_in[4];
    const float* proj_w = (const float*)d_in[5];
    const float* proj_b = (const float*)d_in[6];
    const float* n2_g   = (const float*)d_in[7];
    const float* n2_b   = (const float*)d_in[8];
    const float* mlp_w1 = (const float*)d_in[9];
    const float* mlp_b1 = (const float*)d_in[10];
    const float* mlp_w2 = (const float*)d_in[11];
    const float* mlp_b2 = (const float*)d_in[12];

    float *ywin, *xbhwc, *qkvb, *ow, *x1, *h2, *hmid, *x2;
    cudaGetSymbolAddress((void**)&ywin,  g_ywin);
    cudaGetSymbolAddress((void**)&xbhwc, g_xbhwc);
    cudaGetSymbolAddress((void**)&qkvb,  g_qkv);
    cudaGetSymbolAddress((void**)&ow,    g_ow);
    cudaGetSymbolAddress((void**)&x1,    g_x1);
    cudaGetSymbolAddress((void**)&h2,    g_h2);
    cudaGetSymbolAddress((void**)&hmid,  g_hmid);
    cudaGetSymbolAddress((void**)&x2,    g_x2);

    // 1) LN1 + shift + window partition (+ shortcut in NHWC)
    ln1_kernel<<<BATCH*98, 256>>>(x, n1_g, n1_b, ywin, xbhwc);

    // 2) qkv = ywin @ qkv_w + qkv_b           (100352 x 768 x 256)
    sgemm_k<EPI_BIAS><<<dim3(QKVN/BN, TOK/BM), 256>>>(ywin, qkv_w, qkv_b, qkvb, nullptr, TOK, QKVN, CH);

    // 3) windowed attention
    attn_kernel<<<2048*HEADS, 256>>>(qkvb, ow);

    // 4) x1 = shortcut + unshift(unwindow(ow @ proj_w + proj_b))   (100352 x 256 x 256)
    sgemm_k<EPI_PROJ><<<dim3(CH/BN, TOK/BM), 256>>>(ow, proj_w, proj_b, x1, xbhwc, TOK, CH, CH);

    // 5) h2 = LN2(x1)
    ln2_kernel<<<TOK, 256>>>(x1, n2_g, n2_b, h2);

    // 6) hmid = gelu(h2 @ mlp_w1 + mlp_b1)    (100352 x 1024 x 256)
    sgemm_k<EPI_GELU><<<dim3(HIDDEN/BN, TOK/BM), 256>>>(h2, mlp_w1, mlp_b1, hmid, nullptr, TOK, HIDDEN, CH);

    // 7) x2 = x1 + hmid @ mlp_w2 + mlp_b2     (100352 x 256 x 1024)
    sgemm_k<EPI_RES><<<dim3(CH/BN, TOK/BM), 256>>>(hmid, mlp_w2, mlp_b2, x2, x1, TOK, CH, HIDDEN);

    // 8) (b,hw,c) -> (b,c,h,w)
    transpose_out<<<dim3(HWS/32, CH/32, BATCH), 256>>>(x2, (float*)d_out);
}

// round 2
// speedup vs baseline: 2.1445x; 2.1445x over previous
#include <cuda_runtime.h>
#include <cuda_bf16.h>
#include <math.h>
#include <stdint.h>

// ---------------- problem constants ----------------
#define BATCH 32
#define CH    256
#define HH    56
#define WW    56
#define HWS   (HH*WW)          // 3136
#define TOK   (BATCH*HWS)      // 100352
#define WS7   7
#define SHIFT3 3
#define HEADS 8
#define HDIM  32
#define HIDDEN 1024
#define QKVN  768

// ---------------- scratch (device globals; no allocation allowed) ----------------
__device__ float g_ywin [(size_t)TOK*CH];     // LN1 output, window-token order
__device__ float g_xbhwc[(size_t)TOK*CH];     // shortcut, (b,h,w,c)
__device__ float g_qkv  [(size_t)TOK*QKVN];   // qkv, window-token order
__device__ float g_ow   [(size_t)TOK*CH];     // attention out, window-token order
__device__ float g_x1   [(size_t)TOK*CH];     // shortcut + proj out, (b,h,w,c)
__device__ float g_h2   [(size_t)TOK*CH];     // LN2 out
__device__ float g_hmid [(size_t)TOK*HIDDEN]; // mlp hidden
__device__ float g_x2   [(size_t)TOK*CH];     // final (b,h,w,c)

__device__ __forceinline__ float to_tf32(float x) {
    float r;
    asm("cvt.rna.tf32.f32 %0, %1;" : "=f"(r) : "f"(x));
    return r;
}

// ---------------- kernel 1: LN1 + shift + window partition + NHWC shortcut ----------------
__global__ __launch_bounds__(256) void ln1_kernel(
    const float* __restrict__ x, const float* __restrict__ g, const float* __restrict__ bta,
    float* __restrict__ ywin, float* __restrict__ xbhwc)
{
    __shared__ float ts[256*33];
    __shared__ float cmu[32], crs[32];
    const int blk = blockIdx.x;
    const int b   = blk / 98;
    const int hw0 = (blk % 98) * 32;
    const int tid = threadIdx.x;
    const float* xb = x + (size_t)b*CH*HWS;

    for (int idx = tid; idx < 256*32; idx += 256) {
        int ch = idx >> 5, j = idx & 31;
        ts[ch*33 + j] = xb[(size_t)ch*HWS + hw0 + j];
    }
    __syncthreads();

    {
        int col = tid >> 3, kk = tid & 7;
        float s = 0.f, s2 = 0.f;
        for (int ch = kk; ch < 256; ch += 8) {
            float v = ts[ch*33 + col];
            s += v; s2 += v*v;
        }
        #pragma unroll
        for (int o = 4; o; o >>= 1) {
            s  += __shfl_down_sync(0xffffffffu, s,  o, 8);
            s2 += __shfl_down_sync(0xffffffffu, s2, o, 8);
        }
        if (kk == 0) {
            float mu = s * (1.f/256.f);
            cmu[col] = mu;
            crs[col] = rsqrtf(s2*(1.f/256.f) - mu*mu + 1e-5f);
        }
    }
    __syncthreads();

    const float gg = g[tid], bb = bta[tid];
    for (int j = 0; j < 32; j++) {
        int hw = hw0 + j;
        int h = hw / 56, w = hw % 56;
        int hs = h + (56 - SHIFT3); if (hs >= 56) hs -= 56;
        int wsh = w + (56 - SHIFT3); if (wsh >= 56) wsh -= 56;
        int wi = hs / 7, r = hs % 7;
        int wj = wsh / 7, c = wsh % 7;
        int win = ((b << 3) + wi) * 8 + wj;
        int n = r*7 + c;
        float v = ts[tid*33 + j];
        xbhwc[((size_t)b*HWS + hw)*CH + tid] = v;
        ywin [((size_t)win*49 + n)*CH + tid] = (v - cmu[j]) * crs[j] * gg + bb;
    }
}

// ---------------- tf32 mma GEMM: 128x128 block, 8 warps @ 64x32 ----------------
#define BM 128
#define BN 128
#define BK 16
#define BKP 20       // As row stride (conflict-free fragment loads)
#define BNP 136      // Bs row stride (conflict-free fragment loads)

enum { EPI_BIAS = 0, EPI_PROJ = 1, EPI_GELU = 2, EPI_RES = 3 };

template<int EPI>
__global__ __launch_bounds__(256) void mma_gemm(
    const float* __restrict__ A, const float* __restrict__ B,
    const float* __restrict__ bias, float* __restrict__ C,
    const float* __restrict__ aux,
    int M, int N, int K)
{
    __shared__ float As[2][BM][BKP];   // [m][k]
    __shared__ float Bs[2][BK][BNP];   // [k][n]

    const int tid  = threadIdx.x;
    const int lane = tid & 31, warp = tid >> 5;
    const int g    = lane >> 2, c4 = lane & 3;
    const int wm0  = (warp >> 2) * 64;   // 0 or 64
    const int wn0  = (warp & 3) * 32;    // 0..96
    const int m0   = blockIdx.y * BM, n0 = blockIdx.x * BN;

    const int arow = tid >> 2;          // 0..63
    const int acol = (tid & 3) * 4;     // 0,4,8,12
    const int brow = tid >> 5;          // 0..7
    const int bcol = (tid & 31) * 4;    // 0..124

    float acc[4][4][4];
    #pragma unroll
    for (int i = 0; i < 4; i++)
        #pragma unroll
        for (int j = 0; j < 4; j++)
            #pragma unroll
            for (int r = 0; r < 4; r++) acc[i][j][r] = 0.f;

    float4 rA[2], rB[2];

    // prologue: tile 0 -> regs -> smem buf 0
    #pragma unroll
    for (int h = 0; h < 2; h++) {
        rA[h] = *reinterpret_cast<const float4*>(&A[(size_t)(m0 + arow + h*64)*K + acol]);
        rB[h] = *reinterpret_cast<const float4*>(&B[(size_t)(brow + h*8)*N + n0 + bcol]);
    }
    #pragma unroll
    for (int h = 0; h < 2; h++) {
        float4 va, vb;
        va.x = to_tf32(rA[h].x); va.y = to_tf32(rA[h].y);
        va.z = to_tf32(rA[h].z); va.w = to_tf32(rA[h].w);
        *reinterpret_cast<float4*>(&As[0][arow + h*64][acol]) = va;
        vb.x = to_tf32(rB[h].x); vb.y = to_tf32(rB[h].y);
        vb.z = to_tf32(rB[h].z); vb.w = to_tf32(rB[h].w);
        *reinterpret_cast<float4*>(&Bs[0][brow + h*8][bcol]) = vb;
    }
    __syncthreads();

    const int nt = K / BK;
    for (int t = 0; t < nt; t++) {
        const int buf = t & 1;
        if (t + 1 < nt) {
            const int k0 = (t + 1) * BK;
            #pragma unroll
            for (int h = 0; h < 2; h++) {
                rA[h] = *reinterpret_cast<const float4*>(&A[(size_t)(m0 + arow + h*64)*K + k0 + acol]);
                rB[h] = *reinterpret_cast<const float4*>(&B[(size_t)(k0 + brow + h*8)*N + n0 + bcol]);
            }
        }

        #pragma unroll
        for (int kk = 0; kk < 2; kk++) {
            const int k8 = kk * 8;
            uint32_t af[4][4], bf[4][2];
            #pragma unroll
            for (int mi = 0; mi < 4; mi++) {
                const float* ap = &As[buf][wm0 + mi*16 + g][k8 + c4];
                af[mi][0] = __float_as_uint(ap[0]);
                af[mi][1] = __float_as_uint(ap[8*BKP]);
                af[mi][2] = __float_as_uint(ap[4]);
                af[mi][3] = __float_as_uint(ap[8*BKP + 4]);
            }
            #pragma unroll
            for (int ni = 0; ni < 4; ni++) {
                const float* bp = &Bs[buf][k8 + c4][wn0 + ni*8 + g];
                bf[ni][0] = __float_as_uint(bp[0]);
                bf[ni][1] = __float_as_uint(bp[4*BNP]);
            }
            #pragma unroll
            for (int mi = 0; mi < 4; mi++)
                #pragma unroll
                for (int ni = 0; ni < 4; ni++) {
                    asm volatile(
                        "mma.sync.aligned.m16n8k8.row.col.f32.tf32.tf32.f32 "
                        "{%0,%1,%2,%3}, {%4,%5,%6,%7}, {%8,%9}, {%0,%1,%2,%3};"
                        : "+f"(acc[mi][ni][0]), "+f"(acc[mi][ni][1]),
                          "+f"(acc[mi][ni][2]), "+f"(acc[mi][ni][3])
                        : "r"(af[mi][0]), "r"(af[mi][1]), "r"(af[mi][2]), "r"(af[mi][3]),
                          "r"(bf[ni][0]), "r"(bf[ni][1]));
                }
        }

        if (t + 1 < nt) {
            const int nb = buf ^ 1;
            #pragma unroll
            for (int h = 0; h < 2; h++) {
                float4 va, vb;
                va.x = to_tf32(rA[h].x); va.y = to_tf32(rA[h].y);
                va.z = to_tf32(rA[h].z); va.w = to_tf32(rA[h].w);
                *reinterpret_cast<float4*>(&As[nb][arow + h*64][acol]) = va;
                vb.x = to_tf32(rB[h].x); vb.y = to_tf32(rB[h].y);
                vb.z = to_tf32(rB[h].z); vb.w = to_tf32(rB[h].w);
                *reinterpret_cast<float4*>(&Bs[nb][brow + h*8][bcol]) = vb;
            }
            __syncthreads();
        }
    }

    // -------- epilogue --------
    #pragma unroll
    for (int mi = 0; mi < 4; mi++) {
        #pragma unroll
        for (int h = 0; h < 2; h++) {
            const int m = m0 + wm0 + mi*16 + g + h*8;
            size_t drow = (size_t)m;   // default: row index in token order
            if (EPI == EPI_PROJ) {
                int win = m / 49, n = m % 49;
                int bb = win >> 6;
                int wr = (win >> 3) & 7;
                int wc = win & 7;
                int r = n / 7, cc = n % 7;
                int hh = wr*7 + r + SHIFT3; if (hh >= 56) hh -= 56;
                int wwv = wc*7 + cc + SHIFT3; if (wwv >= 56) wwv -= 56;
                drow = (size_t)bb*HWS + hh*56 + wwv;
            }
            #pragma unroll
            for (int ni = 0; ni < 4; ni++) {
                const int col = n0 + wn0 + ni*8 + 2*c4;
                float v0 = acc[mi][ni][2*h + 0] + bias[col];
                float v1 = acc[mi][ni][2*h + 1] + bias[col + 1];
                float2 out;
                if (EPI == EPI_BIAS) {
                    out.x = v0; out.y = v1;
                    *reinterpret_cast<float2*>(&C[(size_t)m*N + col]) = out;
                } else if (EPI == EPI_PROJ) {
                    out.x = v0 + aux[drow*CH + col];
                    out.y = v1 + aux[drow*CH + col + 1];
                    *reinterpret_cast<float2*>(&C[drow*CH + col]) = out;
                } else if (EPI == EPI_GELU) {
                    out.x = 0.5f * v0 * (1.f + erff(v0 * 0.70710678118654752f));
                    out.y = 0.5f * v1 * (1.f + erff(v1 * 0.70710678118654752f));
                    *reinterpret_cast<float2*>(&C[(size_t)m*N + col]) = out;
                } else { // EPI_RES
                    out.x = v0 + aux[(size_t)m*N + col];
                    out.y = v1 + aux[(size_t)m*N + col + 1];
                    *reinterpret_cast<float2*>(&C[(size_t)m*N + col]) = out;
                }
            }
        }
    }
}

// ---------------- kernel 3: windowed attention, one block per (window, head) ----------------
__global__ __launch_bounds__(256) void attn_kernel(
    const float* __restrict__ qkv, float* __restrict__ o)
{
    __shared__ float qs[49*33], ks[49*33], vs[49*33];
    __shared__ float ps[49*49];
    const int win  = blockIdx.x >> 3;
    const int head = blockIdx.x & 7;
    const int tid  = threadIdx.x;
    const size_t base = (size_t)win*49*QKVN + head*HDIM;

    for (int idx = tid; idx < 49*32; idx += 256) {
        int n = idx >> 5, c = idx & 31;
        size_t rb = base + (size_t)n*QKVN;
        qs[n*33 + c] = qkv[rb + c];
        ks[n*33 + c] = qkv[rb + 256 + c];
        vs[n*33 + c] = qkv[rb + 512 + c];
    }
    __syncthreads();

    const float scale = 0.17677669529663687f; // 32^-0.5
    for (int s = tid; s < 49*49; s += 256) {
        int i = s / 49, j = s % 49;
        float sum = 0.f;
        #pragma unroll
        for (int c = 0; c < 32; c++) sum += qs[i*33 + c] * ks[j*33 + c];
        ps[s] = sum * scale;
    }
    __syncthreads();

    if (tid < 49) {
        float mx = -1e30f;
        #pragma unroll 7
        for (int j = 0; j < 49; j++) mx = fmaxf(mx, ps[tid*49 + j]);
        float sum = 0.f;
        #pragma unroll 7
        for (int j = 0; j < 49; j++) {
            float e = __expf(ps[tid*49 + j] - mx);
            ps[tid*49 + j] = e; sum += e;
        }
        float inv = 1.f / sum;
        #pragma unroll 7
        for (int j = 0; j < 49; j++) ps[tid*49 + j] *= inv;
    }
    __syncthreads();

    for (int idx = tid; idx < 49*32; idx += 256) {
        int i = idx >> 5, c = idx & 31;
        float sum = 0.f;
        #pragma unroll 7
        for (int j = 0; j < 49; j++) sum += ps[i*49 + j] * vs[j*33 + c];
        o[((size_t)win*49 + i)*CH + head*HDIM + c] = sum;
    }
}

// ---------------- kernel 5: LN2 ----------------
__global__ __launch_bounds__(256) void ln2_kernel(
    const float* __restrict__ x, const float* __restrict__ g, const float* __restrict__ bta,
    float* __restrict__ y)
{
    const int row = blockIdx.x;
    const int tid = threadIdx.x;
    float v = x[(size_t)row*CH + tid];
    float s = v, s2 = v*v;
    #pragma unroll
    for (int o = 16; o; o >>= 1) {
        s  += __shfl_down_sync(0xffffffffu, s,  o);
        s2 += __shfl_down_sync(0xffffffffu, s2, o);
    }
    __shared__ float ws[8], ws2[8];
    int wid = tid >> 5, lane = tid & 31;
    if (lane == 0) { ws[wid] = s; ws2[wid] = s2; }
    __syncthreads();
    if (tid == 0) {
        float ts = 0.f, ts2 = 0.f;
        #pragma unroll
        for (int i = 0; i < 8; i++) { ts += ws[i]; ts2 += ws2[i]; }
        float mu = ts * (1.f/256.f);
        ws[0] = mu;
        ws2[0] = rsqrtf(ts2*(1.f/256.f) - mu*mu + 1e-5f);
    }
    __syncthreads();
    float mu = ws[0], rstd = ws2[0];
    y[(size_t)row*CH + tid] = (v - mu) * rstd * g[tid] + bta[tid];
}

// ---------------- kernel 8: (b,hw,c) -> (b,c,hw) ----------------
__global__ __launch_bounds__(256) void transpose_out(
    const float* __restrict__ x2, float* __restrict__ out)
{
    __shared__ float t[32][33];
    const int b   = blockIdx.z;
    const int c0  = blockIdx.y * 32;
    const int hw0 = blockIdx.x * 32;
    const int j = threadIdx.x & 31;
    const int i = threadIdx.x >> 5;
    for (int ii = i; ii < 32; ii += 8)
        t[ii][j] = x2[((size_t)b*HWS + hw0 + ii)*CH + c0 + j];
    __syncthreads();
    for (int ii = i; ii < 32; ii += 8)
        out[((size_t)(b*CH + c0 + ii))*HWS + hw0 + j] = t[j][ii];
}

// ---------------- launch ----------------
extern "C" void kernel_launch(void* const* d_in, const int* in_sizes, int n_in,
                              void* d_out, int out_size)
{
    const float* x      = (const float*)d_in[0];
    const float* n1_g   = (const float*)d_in[1];
    const float* n1_b   = (const float*)d_in[2];
    const float* qkv_w  = (const float*)d_in[3];
    const float* qkv_b  = (const float*)d_in[4];
    const float* proj_w = (const float*)d_in[5];
    const float* proj_b = (const float*)d_in[6];
    const float* n2_g   = (const float*)d_in[7];
    const float* n2_b   = (const float*)d_in[8];
    const float* mlp_w1 = (const float*)d_in[9];
    const float* mlp_b1 = (const float*)d_in[10];
    const float* mlp_w2 = (const float*)d_in[11];
    const float* mlp_b2 = (const float*)d_in[12];

    float *ywin, *xbhwc, *qkvb, *ow, *x1, *h2, *hmid, *x2;
    cudaGetSymbolAddress((void**)&ywin,  g_ywin);
    cudaGetSymbolAddress((void**)&xbhwc, g_xbhwc);
    cudaGetSymbolAddress((void**)&qkvb,  g_qkv);
    cudaGetSymbolAddress((void**)&ow,    g_ow);
    cudaGetSymbolAddress((void**)&x1,    g_x1);
    cudaGetSymbolAddress((void**)&h2,    g_h2);
    cudaGetSymbolAddress((void**)&hmid,  g_hmid);
    cudaGetSymbolAddress((void**)&x2,    g_x2);

    // 1) LN1 + shift + window partition (+ shortcut in NHWC)
    ln1_kernel<<<BATCH*98, 256>>>(x, n1_g, n1_b, ywin, xbhwc);

    // 2) qkv = ywin @ qkv_w + qkv_b           (100352 x 768 x 256)
    mma_gemm<EPI_BIAS><<<dim3(QKVN/BN, TOK/BM), 256>>>(ywin, qkv_w, qkv_b, qkvb, nullptr, TOK, QKVN, CH);

    // 3) windowed attention
    attn_kernel<<<2048*HEADS, 256>>>(qkvb, ow);

    // 4) x1 = shortcut + unshift(unwindow(ow @ proj_w + proj_b))   (100352 x 256 x 256)
    mma_gemm<EPI_PROJ><<<dim3(CH/BN, TOK/BM), 256>>>(ow, proj_w, proj_b, x1, xbhwc, TOK, CH, CH);

    // 5) h2 = LN2(x1)
    ln2_kernel<<<TOK, 256>>>(x1, n2_g, n2_b, h2);

    // 6) hmid = gelu(h2 @ mlp_w1 + mlp_b1)    (100352 x 1024 x 256)
    mma_gemm<EPI_GELU><<<dim3(HIDDEN/BN, TOK/BM), 256>>>(h2, mlp_w1, mlp_b1, hmid, nullptr, TOK, HIDDEN, CH);

    // 7) x2 = x1 + hmid @ mlp_w2 + mlp_b2     (100352 x 256 x 1024)
    mma_gemm<EPI_RES><<<dim3(CH/BN, TOK/BM), 256>>>(hmid, mlp_w2, mlp_b2, x2, x1, TOK, CH, HIDDEN);

    // 8) (b,hw,c) -> (b,c,h,w)
    transpose_out<<<dim3(HWS/32, CH/32, BATCH), 256>>>(x2, (float*)d_out);
}

// round 3
// speedup vs baseline: 2.3841x; 1.1117x over previous
#include <cuda_runtime.h>
#include <cuda_bf16.h>
#include <math.h>
#include <stdint.h>

// ---------------- problem constants ----------------
#define BATCH 32
#define CH    256
#define HH    56
#define WW    56
#define HWS   (HH*WW)          // 3136
#define TOK   (BATCH*HWS)      // 100352
#define SHIFT3 3
#define HEADS 8
#define HDIM  32
#define HIDDEN 1024
#define QKVN  768

// ---------------- scratch ----------------
__device__ float g_ywin [(size_t)TOK*CH];
__device__ float g_xbhwc[(size_t)TOK*CH];
__device__ float g_qkv  [(size_t)TOK*QKVN];
__device__ float g_ow   [(size_t)TOK*CH];
__device__ float g_x1   [(size_t)TOK*CH];
__device__ float g_h2   [(size_t)TOK*CH];
__device__ float g_hmid [(size_t)TOK*HIDDEN];
__device__ float g_x2   [(size_t)TOK*CH];
// tf32-rounded weight copies
__device__ float g_wqkv [CH*QKVN];
__device__ float g_wproj[CH*CH];
__device__ float g_w1   [CH*HIDDEN];
__device__ float g_w2   [HIDDEN*CH];

__device__ __forceinline__ float to_tf32(float x) {
    float r;
    asm("cvt.rna.tf32.f32 %0, %1;" : "=f"(r) : "f"(x));
    return r;
}

__global__ void round_tf32(const float* __restrict__ in, float* __restrict__ out, int n) {
    int i = blockIdx.x*256 + threadIdx.x;
    if (i < n) out[i] = to_tf32(in[i]);
}

// ---------------- kernel 1: LN1 + shift + window partition + NHWC shortcut ----------------
__global__ __launch_bounds__(256) void ln1_kernel(
    const float* __restrict__ x, const float* __restrict__ g, const float* __restrict__ bta,
    float* __restrict__ ywin, float* __restrict__ xbhwc)
{
    __shared__ float ts[256*33];
    __shared__ float cmu[32], crs[32];
    const int blk = blockIdx.x;
    const int b   = blk / 98;
    const int hw0 = (blk % 98) * 32;
    const int tid = threadIdx.x;
    const float* xb = x + (size_t)b*CH*HWS;

    for (int idx = tid; idx < 256*32; idx += 256) {
        int ch = idx >> 5, j = idx & 31;
        ts[ch*33 + j] = xb[(size_t)ch*HWS + hw0 + j];
    }
    __syncthreads();

    {
        int col = tid >> 3, kk = tid & 7;
        float s = 0.f, s2 = 0.f;
        for (int ch = kk; ch < 256; ch += 8) {
            float v = ts[ch*33 + col];
            s += v; s2 += v*v;
        }
        #pragma unroll
        for (int o = 4; o; o >>= 1) {
            s  += __shfl_down_sync(0xffffffffu, s,  o, 8);
            s2 += __shfl_down_sync(0xffffffffu, s2, o, 8);
        }
        if (kk == 0) {
            float mu = s * (1.f/256.f);
            cmu[col] = mu;
            crs[col] = rsqrtf(s2*(1.f/256.f) - mu*mu + 1e-5f);
        }
    }
    __syncthreads();

    const float gg = g[tid], bb = bta[tid];
    for (int j = 0; j < 32; j++) {
        int hw = hw0 + j;
        int h = hw / 56, w = hw % 56;
        int hs = h + (56 - SHIFT3); if (hs >= 56) hs -= 56;
        int wsh = w + (56 - SHIFT3); if (wsh >= 56) wsh -= 56;
        int wi = hs / 7, r = hs % 7;
        int wj = wsh / 7, c = wsh % 7;
        int win = ((b << 3) + wi) * 8 + wj;
        int n = r*7 + c;
        float v = ts[tid*33 + j];
        xbhwc[((size_t)b*HWS + hw)*CH + tid] = v;
        ywin [((size_t)win*49 + n)*CH + tid] = to_tf32((v - cmu[j]) * crs[j] * gg + bb);
    }
}

// ---------------- tf32 mma GEMM, cp.async 3-stage ----------------
#define BM 128
#define BN 128
#define BK 32
#define STAGES 3
#define BNP 132
#define A_STAGE_F (BM*BK)        // 4096 floats, swizzled [128][32]
#define B_STAGE_F (BK*BNP)       // 4224 floats
#define SMEM_FLOATS (STAGES*(A_STAGE_F + B_STAGE_F))  // 24960 -> 99840 B

enum { EPI_BIAS = 0, EPI_PROJ = 1, EPI_GELU = 2, EPI_RES = 3 };

__device__ __forceinline__ void cpasync16(uint32_t dst, const void* src) {
    asm volatile("cp.async.cg.shared.global [%0], [%1], 16;" :: "r"(dst), "l"(src));
}

template<int EPI>
__global__ __launch_bounds__(256, 2) void mma_gemm(
    const float* __restrict__ A, const float* __restrict__ B,
    const float* __restrict__ bias, float* __restrict__ C,
    const float* __restrict__ aux,
    int M, int N, int K)
{
    extern __shared__ float sm[];
    const uint32_t smb = (uint32_t)__cvta_generic_to_shared(sm);

    const int tid  = threadIdx.x;
    const int lane = tid & 31, warp = tid >> 5;
    const int g    = lane >> 2, c4 = lane & 3;
    const int wm0  = (warp >> 2) * 64;
    const int wn0  = (warp & 3) * 32;
    const int m0   = blockIdx.y * BM, n0 = blockIdx.x * BN;

    // cp.async thread mapping
    const int arow = tid >> 3;            // 0..31 (+32 per iter), 8 chunks/row
    const int ac   = tid & 7;             // chunk in row
    const int adst = (ac ^ (arow & 7));   // swizzled chunk
    const int brow = tid >> 5;            // 0..7 (+8 per iter), 32 chunks/row
    const int bc   = tid & 31;

    const int nt = K / BK;

    float acc[4][4][4];
    #pragma unroll
    for (int i = 0; i < 4; i++)
        #pragma unroll
        for (int j = 0; j < 4; j++)
            #pragma unroll
            for (int r = 0; r < 4; r++) acc[i][j][r] = 0.f;

    // issue stage t
    auto issue = [&](int t) {
        const int s = t % STAGES;
        const int k0 = t * BK;
        const uint32_t abase = smb + (uint32_t)(s*A_STAGE_F)*4;
        const uint32_t bbase = smb + (uint32_t)(STAGES*A_STAGE_F + s*B_STAGE_F)*4;
        #pragma unroll
        for (int i = 0; i < 4; i++) {
            int r = arow + 32*i;
            cpasync16(abase + (uint32_t)(r*BK + adst*4)*4,
                      &A[(size_t)(m0 + r)*K + k0 + ac*4]);
        }
        #pragma unroll
        for (int i = 0; i < 4; i++) {
            int r = brow + 8*i;
            cpasync16(bbase + (uint32_t)(r*BNP + bc*4)*4,
                      &B[(size_t)(k0 + r)*N + n0 + bc*4]);
        }
    };

    #pragma unroll
    for (int s = 0; s < STAGES-1; s++) {
        issue(s);
        asm volatile("cp.async.commit_group;");
    }

    for (int t = 0; t < nt; t++) {
        asm volatile("cp.async.wait_group %0;" :: "n"(STAGES-2));
        __syncthreads();
        if (t + STAGES - 1 < nt) issue(t + STAGES - 1);
        asm volatile("cp.async.commit_group;");

        const float* as = sm + (t % STAGES)*A_STAGE_F;
        const float* bs = sm + STAGES*A_STAGE_F + (t % STAGES)*B_STAGE_F;

        #pragma unroll
        for (int kk = 0; kk < 4; kk++) {
            const int k8  = kk*8;
            const int ch0 = k8 >> 2;
            uint32_t af[4][4], bf[4][2];
            #pragma unroll
            for (int mi = 0; mi < 4; mi++) {
                const int r0 = wm0 + mi*16 + g;
                const int o0 = ((ch0     ^ g) << 2) + c4;
                const int o1 = (((ch0+1) ^ g) << 2) + c4;
                af[mi][0] = __float_as_uint(as[ r0      *BK + o0]);
                af[mi][1] = __float_as_uint(as[(r0 + 8) *BK + o0]);
                af[mi][2] = __float_as_uint(as[ r0      *BK + o1]);
                af[mi][3] = __float_as_uint(as[(r0 + 8) *BK + o1]);
            }
            #pragma unroll
            for (int ni = 0; ni < 4; ni++) {
                const int col = wn0 + ni*8 + g;
                bf[ni][0] = __float_as_uint(bs[(k8 + c4    )*BNP + col]);
                bf[ni][1] = __float_as_uint(bs[(k8 + c4 + 4)*BNP + col]);
            }
            #pragma unroll
            for (int mi = 0; mi < 4; mi++)
                #pragma unroll
                for (int ni = 0; ni < 4; ni++) {
                    asm volatile(
                        "mma.sync.aligned.m16n8k8.row.col.f32.tf32.tf32.f32 "
                        "{%0,%1,%2,%3}, {%4,%5,%6,%7}, {%8,%9}, {%0,%1,%2,%3};"
                        : "+f"(acc[mi][ni][0]), "+f"(acc[mi][ni][1]),
                          "+f"(acc[mi][ni][2]), "+f"(acc[mi][ni][3])
                        : "r"(af[mi][0]), "r"(af[mi][1]), "r"(af[mi][2]), "r"(af[mi][3]),
                          "r"(bf[ni][0]), "r"(bf[ni][1]));
                }
        }
    }

    // -------- epilogue --------
    #pragma unroll
    for (int mi = 0; mi < 4; mi++) {
        #pragma unroll
        for (int h = 0; h < 2; h++) {
            const int m = m0 + wm0 + mi*16 + g + h*8;
            size_t drow = (size_t)m;
            if (EPI == EPI_PROJ) {
                int win = m / 49, n = m % 49;
                int bb = win >> 6;
                int wr = (win >> 3) & 7;
                int wc = win & 7;
                int r = n / 7, cc = n % 7;
                int hh = wr*7 + r + SHIFT3; if (hh >= 56) hh -= 56;
                int wwv = wc*7 + cc + SHIFT3; if (wwv >= 56) wwv -= 56;
                drow = (size_t)bb*HWS + hh*56 + wwv;
            }
            #pragma unroll
            for (int ni = 0; ni < 4; ni++) {
                const int col = n0 + wn0 + ni*8 + 2*c4;
                float v0 = acc[mi][ni][2*h + 0] + bias[col];
                float v1 = acc[mi][ni][2*h + 1] + bias[col + 1];
                float2 out;
                if (EPI == EPI_BIAS) {
                    out.x = v0; out.y = v1;
                    *reinterpret_cast<float2*>(&C[(size_t)m*N + col]) = out;
                } else if (EPI == EPI_PROJ) {
                    out.x = v0 + aux[drow*CH + col];
                    out.y = v1 + aux[drow*CH + col + 1];
                    *reinterpret_cast<float2*>(&C[drow*CH + col]) = out;
                } else if (EPI == EPI_GELU) {
                    out.x = to_tf32(0.5f * v0 * (1.f + erff(v0 * 0.70710678118654752f)));
                    out.y = to_tf32(0.5f * v1 * (1.f + erff(v1 * 0.70710678118654752f)));
                    *reinterpret_cast<float2*>(&C[(size_t)m*N + col]) = out;
                } else { // EPI_RES
                    out.x = v0 + aux[(size_t)m*N + col];
                    out.y = v1 + aux[(size_t)m*N + col + 1];
                    *reinterpret_cast<float2*>(&C[(size_t)m*N + col]) = out;
                }
            }
        }
    }
}

// ---------------- kernel 3: windowed attention ----------------
__global__ __launch_bounds__(256) void attn_kernel(
    const float* __restrict__ qkv, float* __restrict__ o)
{
    __shared__ float qs[49*33], ks[49*33], vs[49*33];
    __shared__ float ps[49*49];
    const int win  = blockIdx.x >> 3;
    const int head = blockIdx.x & 7;
    const int tid  = threadIdx.x;
    const size_t base = (size_t)win*49*QKVN + head*HDIM;

    for (int idx = tid; idx < 49*32; idx += 256) {
        int n = idx >> 5, c = idx & 31;
        size_t rb = base + (size_t)n*QKVN;
        qs[n*33 + c] = qkv[rb + c];
        ks[n*33 + c] = qkv[rb + 256 + c];
        vs[n*33 + c] = qkv[rb + 512 + c];
    }
    __syncthreads();

    const float scale = 0.17677669529663687f;
    for (int s = tid; s < 49*49; s += 256) {
        int i = s / 49, j = s % 49;
        float sum = 0.f;
        #pragma unroll
        for (int c = 0; c < 32; c++) sum += qs[i*33 + c] * ks[j*33 + c];
        ps[s] = sum * scale;
    }
    __syncthreads();

    if (tid < 49) {
        float mx = -1e30f;
        #pragma unroll 7
        for (int j = 0; j < 49; j++) mx = fmaxf(mx, ps[tid*49 + j]);
        float sum = 0.f;
        #pragma unroll 7
        for (int j = 0; j < 49; j++) {
            float e = __expf(ps[tid*49 + j] - mx);
            ps[tid*49 + j] = e; sum += e;
        }
        float inv = 1.f / sum;
        #pragma unroll 7
        for (int j = 0; j < 49; j++) ps[tid*49 + j] *= inv;
    }
    __syncthreads();

    for (int idx = tid; idx < 49*32; idx += 256) {
        int i = idx >> 5, c = idx & 31;
        float sum = 0.f;
        #pragma unroll 7
        for (int j = 0; j < 49; j++) sum += ps[i*49 + j] * vs[j*33 + c];
        o[((size_t)win*49 + i)*CH + head*HDIM + c] = to_tf32(sum);
    }
}

// ---------------- kernel 5: LN2 ----------------
__global__ __launch_bounds__(256) void ln2_kernel(
    const float* __restrict__ x, const float* __restrict__ g, const float* __restrict__ bta,
    float* __restrict__ y)
{
    const int row = blockIdx.x;
    const int tid = threadIdx.x;
    float v = x[(size_t)row*CH + tid];
    float s = v, s2 = v*v;
    #pragma unroll
    for (int o = 16; o; o >>= 1) {
        s  += __shfl_down_sync(0xffffffffu, s,  o);
        s2 += __shfl_down_sync(0xffffffffu, s2, o);
    }
    __shared__ float ws[8], ws2[8];
    int wid = tid >> 5, lane = tid & 31;
    if (lane == 0) { ws[wid] = s; ws2[wid] = s2; }
    __syncthreads();
    if (tid == 0) {
        float ts = 0.f, ts2 = 0.f;
        #pragma unroll
        for (int i = 0; i < 8; i++) { ts += ws[i]; ts2 += ws2[i]; }
        float mu = ts * (1.f/256.f);
        ws[0] = mu;
        ws2[0] = rsqrtf(ts2*(1.f/256.f) - mu*mu + 1e-5f);
    }
    __syncthreads();
    float mu = ws[0], rstd = ws2[0];
    y[(size_t)row*CH + tid] = to_tf32((v - mu) * rstd * g[tid] + bta[tid]);
}

// ---------------- kernel 8: (b,hw,c) -> (b,c,hw) ----------------
__global__ __launch_bounds__(256) void transpose_out(
    const float* __restrict__ x2, float* __restrict__ out)
{
    __shared__ float t[32][33];
    const int b   = blockIdx.z;
    const int c0  = blockIdx.y * 32;
    const int hw0 = blockIdx.x * 32;
    const int j = threadIdx.x & 31;
    const int i = threadIdx.x >> 5;
    for (int ii = i; ii < 32; ii += 8)
        t[ii][j] = x2[((size_t)b*HWS + hw0 + ii)*CH + c0 + j];
    __syncthreads();
    for (int ii = i; ii < 32; ii += 8)
        out[((size_t)(b*CH + c0 + ii))*HWS + hw0 + j] = t[j][ii];
}

// ---------------- launch ----------------
extern "C" void kernel_launch(void* const* d_in, const int* in_sizes, int n_in,
                              void* d_out, int out_size)
{
    const float* x      = (const float*)d_in[0];
    const float* n1_g   = (const float*)d_in[1];
    const float* n1_b   = (const float*)d_in[2];
    const float* qkv_w  = (const float*)d_in[3];
    const float* qkv_b  = (const float*)d_in[4];
    const float* proj_w = (const float*)d_in[5];
    const float* proj_b = (const float*)d_in[6];
    const float* n2_g   = (const float*)d_in[7];
    const float* n2_b   = (const float*)d_in[8];
    const float* mlp_w1 = (const float*)d_in[9];
    const float* mlp_b1 = (const float*)d_in[10];
    const float* mlp_w2 = (const float*)d_in[11];
    const float* mlp_b2 = (const float*)d_in[12];

    float *ywin, *xbhwc, *qkvb, *ow, *x1, *h2, *hmid, *x2;
    float *wqkv, *wproj, *w1, *w2;
    cudaGetSymbolAddress((void**)&ywin,  g_ywin);
    cudaGetSymbolAddress((void**)&xbhwc, g_xbhwc);
    cudaGetSymbolAddress((void**)&qkvb,  g_qkv);
    cudaGetSymbolAddress((void**)&ow,    g_ow);
    cudaGetSymbolAddress((void**)&x1,    g_x1);
    cudaGetSymbolAddress((void**)&h2,    g_h2);
    cudaGetSymbolAddress((void**)&hmid,  g_hmid);
    cudaGetSymbolAddress((void**)&x2,    g_x2);
    cudaGetSymbolAddress((void**)&wqkv,  g_wqkv);
    cudaGetSymbolAddress((void**)&wproj, g_wproj);
    cudaGetSymbolAddress((void**)&w1,    g_w1);
    cudaGetSymbolAddress((void**)&w2,    g_w2);

    const int smem_bytes = SMEM_FLOATS * 4;
    static bool attr_done = false;
    if (!attr_done) {
        cudaFuncSetAttribute(mma_gemm<EPI_BIAS>, cudaFuncAttributeMaxDynamicSharedMemorySize, smem_bytes);
        cudaFuncSetAttribute(mma_gemm<EPI_PROJ>, cudaFuncAttributeMaxDynamicSharedMemorySize, smem_bytes);
        cudaFuncSetAttribute(mma_gemm<EPI_GELU>, cudaFuncAttributeMaxDynamicSharedMemorySize, smem_bytes);
        cudaFuncSetAttribute(mma_gemm<EPI_RES>,  cudaFuncAttributeMaxDynamicSharedMemorySize, smem_bytes);
        attr_done = true;
    }

    // 0) round weights to tf32 copies
    round_tf32<<<(CH*QKVN   + 255)/256, 256>>>(qkv_w,  wqkv,  CH*QKVN);
    round_tf32<<<(CH*CH     + 255)/256, 256>>>(proj_w, wproj, CH*CH);
    round_tf32<<<(CH*HIDDEN + 255)/256, 256>>>(mlp_w1, w1,    CH*HIDDEN);
    round_tf32<<<(HIDDEN*CH + 255)/256, 256>>>(mlp_w2, w2,    HIDDEN*CH);

    // 1) LN1 + shift + window partition (+ shortcut NHWC)
    ln1_kernel<<<BATCH*98, 256>>>(x, n1_g, n1_b, ywin, xbhwc);

    // 2) qkv = ywin @ wqkv + qkv_b
    mma_gemm<EPI_BIAS><<<dim3(QKVN/BN, TOK/BM), 256, smem_bytes>>>(ywin, wqkv, qkv_b, qkvb, nullptr, TOK, QKVN, CH);

    // 3) windowed attention
    attn_kernel<<<2048*HEADS, 256>>>(qkvb, ow);

    // 4) x1 = shortcut + unshift(unwindow(ow @ wproj + proj_b))
    mma_gemm<EPI_PROJ><<<dim3(CH/BN, TOK/BM), 256, smem_bytes>>>(ow, wproj, proj_b, x1, xbhwc, TOK, CH, CH);

    // 5) h2 = LN2(x1)
    ln2_kernel<<<TOK, 256>>>(x1, n2_g, n2_b, h2);

    // 6) hmid = gelu(h2 @ w1 + mlp_b1)
    mma_gemm<EPI_GELU><<<dim3(HIDDEN/BN, TOK/BM), 256, smem_bytes>>>(h2, w1, mlp_b1, hmid, nullptr, TOK, HIDDEN, CH);

    // 7) x2 = x1 + hmid @ w2 + mlp_b2
    mma_gemm<EPI_RES><<<dim3(CH/BN, TOK/BM), 256, smem_bytes>>>(hmid, w2, mlp_b2, x2, x1, TOK, CH, HIDDEN);

    // 8) (b,hw,c) -> (b,c,h,w)
    transpose_out<<<dim3(HWS/32, CH/32, BATCH), 256>>>(x2, (float*)d_out);
}

// round 5
// speedup vs baseline: 2.8144x; 1.1805x over previous
#include <cuda_runtime.h>
#include <cuda_bf16.h>
#include <math.h>
#include <stdint.h>

// ---------------- problem constants ----------------
#define BATCH 32
#define CH    256
#define HWS   3136
#define TOK   100352
#define SHIFT3 3
#define HEADS 8
#define HDIM  32
#define HIDDEN 1024
#define QKVN  768

// ---------------- scratch ----------------
__device__ float g_ywin [(size_t)TOK*CH];
__device__ float g_qkv  [(size_t)TOK*QKVN];
__device__ float g_ow   [(size_t)TOK*CH];
__device__ float g_x1   [(size_t)TOK*CH];
__device__ float g_h2   [(size_t)TOK*CH];
__device__ float g_hmid [(size_t)TOK*HIDDEN];
// tf32-rounded, TRANSPOSED weight copies: [N][K]
__device__ float g_wqkv [QKVN*CH];
__device__ float g_wproj[CH*CH];
__device__ float g_w1   [HIDDEN*CH];
__device__ float g_w2   [CH*HIDDEN];

__device__ __forceinline__ float to_tf32(float x) {
    float r;
    asm("cvt.rna.tf32.f32 %0, %1;" : "=f"(r) : "f"(x));
    return r;
}

__device__ __forceinline__ void cpasync16(uint32_t dst, const void* src) {
    asm volatile("cp.async.cg.shared.global [%0], [%1], 16;" :: "r"(dst), "l"(src));
}

// ---------------- prep: weight transpose + tf32 round ([K][N] -> [N][K]) ----------------
__global__ __launch_bounds__(256) void transpose_round(
    const float* __restrict__ w, float* __restrict__ wt, int K, int N)
{
    __shared__ float t[32][33];
    const int k0 = blockIdx.y * 32, n0 = blockIdx.x * 32;
    const int x = threadIdx.x & 31, y = threadIdx.x >> 5;
    for (int yy = y; yy < 32; yy += 8)
        t[yy][x] = w[(size_t)(k0 + yy)*N + n0 + x];
    __syncthreads();
    for (int yy = y; yy < 32; yy += 8)
        wt[(size_t)(n0 + yy)*K + k0 + x] = to_tf32(t[x][yy]);
}

// ---------------- kernel 1: LN1 + shift + window partition ----------------
__global__ __launch_bounds__(256) void ln1_kernel(
    const float* __restrict__ x, const float* __restrict__ g, const float* __restrict__ bta,
    float* __restrict__ ywin)
{
    __shared__ float ts[256*33];
    __shared__ float cmu[32], crs[32];
    const int blk = blockIdx.x;
    const int b   = blk / 98;
    const int hw0 = (blk % 98) * 32;
    const int tid = threadIdx.x;
    const float* xb = x + (size_t)b*CH*HWS;

    for (int idx = tid; idx < 256*32; idx += 256) {
        int ch = idx >> 5, j = idx & 31;
        ts[ch*33 + j] = xb[(size_t)ch*HWS + hw0 + j];
    }
    __syncthreads();

    {
        int col = tid >> 3, kk = tid & 7;
        float s = 0.f, s2 = 0.f;
        for (int ch = kk; ch < 256; ch += 8) {
            float v = ts[ch*33 + col];
            s += v; s2 += v*v;
        }
        #pragma unroll
        for (int o = 4; o; o >>= 1) {
            s  += __shfl_down_sync(0xffffffffu, s,  o, 8);
            s2 += __shfl_down_sync(0xffffffffu, s2, o, 8);
        }
        if (kk == 0) {
            float mu = s * (1.f/256.f);
            cmu[col] = mu;
            crs[col] = rsqrtf(s2*(1.f/256.f) - mu*mu + 1e-5f);
        }
    }
    __syncthreads();

    const float gg = g[tid], bb = bta[tid];
    for (int j = 0; j < 32; j++) {
        int hw = hw0 + j;
        int h = hw / 56, w = hw % 56;
        int hs = h + (56 - SHIFT3); if (hs >= 56) hs -= 56;
        int wsh = w + (56 - SHIFT3); if (wsh >= 56) wsh -= 56;
        int wi = hs / 7, r = hs % 7;
        int wj = wsh / 7, c = wsh % 7;
        int win = ((b << 3) + wi) * 8 + wj;
        int n = r*7 + c;
        ywin[((size_t)win*49 + n)*CH + tid] = to_tf32((ts[tid*33 + j] - cmu[j]) * crs[j] * gg + bb);
    }
}

// ---------------- tf32 mma GEMM: CTA 128x256, warp 64x64, cp.async 3-stage ----------------
// Both A and B tiles stored [row][32 k-floats], 16B-chunk XOR swizzle (chunk ^ row&7).
#define BK 32
#define STAGES 3
#define A_STAGE_F (128*32)
#define B_STAGE_F (256*32)
#define STAGE_F   (A_STAGE_F + B_STAGE_F)
#define SMEM_DYN  (STAGES*STAGE_F*4)

enum { EPI_BIAS = 0, EPI_PROJ = 1, EPI_GELU = 2, EPI_RES = 3 };

template<int EPI>
__global__ __launch_bounds__(256) void mma_gemm(
    const float* __restrict__ A, const float* __restrict__ BT,
    const float* __restrict__ bias, float* __restrict__ C,
    const float* __restrict__ aux,
    int M, int N, int K)
{
    extern __shared__ float sm[];
    const uint32_t smb = (uint32_t)__cvta_generic_to_shared(sm);

    const int tid  = threadIdx.x;
    const int lane = tid & 31, warp = tid >> 5;
    const int g    = lane >> 2, c4 = lane & 3;
    const int wm0  = (warp >> 2) * 64;    // 0,64
    const int wn0  = (warp & 3) * 64;     // 0..192
    const int m0   = blockIdx.y * 128, n0 = blockIdx.x * 256;

    const int r  = tid >> 3;              // 0..31
    const int c  = tid & 7;               // 16B chunk

    float acc[4][8][4];
    #pragma unroll
    for (int i = 0; i < 4; i++)
        #pragma unroll
        for (int j = 0; j < 8; j++)
            #pragma unroll
            for (int k = 0; k < 4; k++) acc[i][j][k] = 0.f;

    auto fill = [&](int t) {
        const int s = t % STAGES;
        const uint32_t ab = smb + (uint32_t)(s*STAGE_F)*4;
        const uint32_t bb = ab + A_STAGE_F*4;
        const int k0 = t * BK;
        #pragma unroll
        for (int i = 0; i < 4; i++) {
            int rr = r + 32*i;
            cpasync16(ab + (uint32_t)(rr*128) + (uint32_t)((c ^ (rr & 7)) << 4),
                      &A[(size_t)(m0 + rr)*K + k0 + c*4]);
        }
        #pragma unroll
        for (int i = 0; i < 8; i++) {
            int rr = r + 32*i;
            cpasync16(bb + (uint32_t)(rr*128) + (uint32_t)((c ^ (rr & 7)) << 4),
                      &BT[(size_t)(n0 + rr)*K + k0 + c*4]);
        }
    };

    const int nt = K / BK;
    #pragma unroll
    for (int s = 0; s < STAGES-1; s++) {
        fill(s);
        asm volatile("cp.async.commit_group;");
    }

    for (int t = 0; t < nt; t++) {
        asm volatile("cp.async.wait_group %0;" :: "n"(STAGES-2));
        __syncthreads();
        if (t + STAGES - 1 < nt) fill(t + STAGES - 1);
        asm volatile("cp.async.commit_group;");

        const float* as = sm + (t % STAGES)*STAGE_F;
        const float* bs = as + A_STAGE_F;

        #pragma unroll
        for (int kk = 0; kk < 4; kk++) {
            const int ch  = (((2*kk)   ^ g) << 2) + c4;
            const int ch2 = (((2*kk+1) ^ g) << 2) + c4;
            uint32_t af[4][4], bf[8][2];
            #pragma unroll
            for (int mi = 0; mi < 4; mi++) {
                const int R0 = wm0 + mi*16 + g;
                af[mi][0] = __float_as_uint(as[ R0     *32 + ch ]);
                af[mi][1] = __float_as_uint(as[(R0 + 8)*32 + ch ]);
                af[mi][2] = __float_as_uint(as[ R0     *32 + ch2]);
                af[mi][3] = __float_as_uint(as[(R0 + 8)*32 + ch2]);
            }
            #pragma unroll
            for (int ni = 0; ni < 8; ni++) {
                const int N0 = wn0 + ni*8 + g;
                bf[ni][0] = __float_as_uint(bs[N0*32 + ch ]);
                bf[ni][1] = __float_as_uint(bs[N0*32 + ch2]);
            }
            #pragma unroll
            for (int mi = 0; mi < 4; mi++)
                #pragma unroll
                for (int ni = 0; ni < 8; ni++) {
                    asm volatile(
                        "mma.sync.aligned.m16n8k8.row.col.f32.tf32.tf32.f32 "
                        "{%0,%1,%2,%3}, {%4,%5,%6,%7}, {%8,%9}, {%0,%1,%2,%3};"
                        : "+f"(acc[mi][ni][0]), "+f"(acc[mi][ni][1]),
                          "+f"(acc[mi][ni][2]), "+f"(acc[mi][ni][3])
                        : "r"(af[mi][0]), "r"(af[mi][1]), "r"(af[mi][2]), "r"(af[mi][3]),
                          "r"(bf[ni][0]), "r"(bf[ni][1]));
                }
        }
    }

    // -------- epilogue --------
    #pragma unroll
    for (int mi = 0; mi < 4; mi++) {
        #pragma unroll
        for (int h = 0; h < 2; h++) {
            const int m = m0 + wm0 + mi*16 + g + 8*h;
            // per-row precompute
            int bq = 0, sp = 0;                  // batch, spatial offset
            if (EPI == EPI_PROJ) {
                int win = m / 49, n = m % 49;
                bq = win >> 6;
                int wr = (win >> 3) & 7;
                int wc = win & 7;
                int rr = n / 7, cc = n % 7;
                int hh = wr*7 + rr + SHIFT3; if (hh >= 56) hh -= 56;
                int wwv = wc*7 + cc + SHIFT3; if (wwv >= 56) wwv -= 56;
                sp = hh*56 + wwv;
            } else if (EPI == EPI_RES) {
                bq = m / HWS; sp = m % HWS;
            }
            #pragma unroll
            for (int ni = 0; ni < 8; ni++) {
                const int col = n0 + wn0 + ni*8 + 2*c4;
                float v0 = acc[mi][ni][2*h + 0] + bias[col];
                float v1 = acc[mi][ni][2*h + 1] + bias[col + 1];
                if (EPI == EPI_BIAS) {
                    float2 out; out.x = v0; out.y = v1;
                    *reinterpret_cast<float2*>(&C[(size_t)m*N + col]) = out;
                } else if (EPI == EPI_PROJ) {
                    // shortcut read from NCHW x, scatter to (b,hw,c)
                    size_t drow = (size_t)bq*HWS + sp;
                    float2 out;
                    out.x = v0 + aux[((size_t)(bq*CH + col    ))*HWS + sp];
                    out.y = v1 + aux[((size_t)(bq*CH + col + 1))*HWS + sp];
                    *reinterpret_cast<float2*>(&C[drow*CH + col]) = out;
                } else if (EPI == EPI_GELU) {
                    float2 out;
                    out.x = to_tf32(0.5f*v0*(1.f + erff(v0*0.70710678118654752f)));
                    out.y = to_tf32(0.5f*v1*(1.f + erff(v1*0.70710678118654752f)));
                    *reinterpret_cast<float2*>(&C[(size_t)m*N + col]) = out;
                } else { // EPI_RES: residual + write NCHW output directly
                    float2 a = *reinterpret_cast<const float2*>(&aux[(size_t)m*N + col]);
                    C[((size_t)(bq*CH + col    ))*HWS + sp] = v0 + a.x;
                    C[((size_t)(bq*CH + col + 1))*HWS + sp] = v1 + a.y;
                }
            }
        }
    }
}

// ---------------- kernel 3: windowed attention (blocked scalar) ----------------
__global__ __launch_bounds__(256) void attn_kernel(
    const float* __restrict__ qkv, float* __restrict__ o)
{
    __shared__ float qs[49*33], ks[49*33], vs[49*33];
    __shared__ float ps[52*52];
    const int win  = blockIdx.x >> 3;
    const int head = blockIdx.x & 7;
    const int tid  = threadIdx.x;
    const int w    = tid >> 5, lane = tid & 31;
    const size_t base = (size_t)win*49*QKVN + head*HDIM;

    for (int idx = tid; idx < 49*32; idx += 256) {
        int n = idx >> 5, c = idx & 31;
        size_t rb = base + (size_t)n*QKVN;
        qs[n*33 + c] = qkv[rb + c];
        ks[n*33 + c] = qkv[rb + 256 + c];
        vs[n*33 + c] = qkv[rb + 512 + c];
    }
    __syncthreads();

    const float scale = 0.17677669529663687f;
    const bool hasj1 = (lane + 32) < 49;

    // QK^T: 25 row-pair slots, warp handles slots w, w+8, w+16, w+24
    for (int p = w; p < 25; p += 8) {
        const int i0 = 2*p;
        const int i1 = (i0 + 1 < 49) ? i0 + 1 : 48;
        float s00 = 0.f, s01 = 0.f, s10 = 0.f, s11 = 0.f;
        #pragma unroll
        for (int c = 0; c < 32; c++) {
            float q0 = qs[i0*33 + c];
            float q1 = qs[i1*33 + c];
            float k0 = ks[lane*33 + c];
            s00 += q0*k0; s10 += q1*k0;
            if (hasj1) {
                float k1 = ks[(lane+32)*33 + c];
                s01 += q0*k1; s11 += q1*k1;
            }
        }
        ps[i0*52 + lane] = s00*scale;
        if (hasj1) ps[i0*52 + lane + 32] = s01*scale;
        if (i1 != i0) {
            ps[i1*52 + lane] = s10*scale;
            if (hasj1) ps[i1*52 + lane + 32] = s11*scale;
        }
    }
    __syncthreads();

    // softmax: warp per row
    for (int i = w; i < 49; i += 8) {
        float v0 = ps[i*52 + lane];
        float v1 = hasj1 ? ps[i*52 + lane + 32] : -1e30f;
        float mx = fmaxf(v0, v1);
        #pragma unroll
        for (int off = 16; off; off >>= 1)
            mx = fmaxf(mx, __shfl_xor_sync(0xffffffffu, mx, off));
        float e0 = __expf(v0 - mx);
        float e1 = hasj1 ? __expf(v1 - mx) : 0.f;
        float sum = e0 + e1;
        #pragma unroll
        for (int off = 16; off; off >>= 1)
            sum += __shfl_xor_sync(0xffffffffu, sum, off);
        float inv = 1.f / sum;
        ps[i*52 + lane] = e0*inv;
        if (hasj1) ps[i*52 + lane + 32] = e1*inv;
    }
    __syncthreads();

    // AV: 13 slots of 4 rows, lane = channel c
    for (int s = w; s < 13; s += 8) {
        const int i0 = 4*s;
        float a0 = 0.f, a1 = 0.f, a2 = 0.f, a3 = 0.f;
        for (int j = 0; j < 49; j++) {
            float v = vs[j*33 + lane];
            a0 += ps[(i0+0)*52 + j] * v;
            a1 += ps[(i0+1)*52 + j] * v;
            a2 += ps[(i0+2)*52 + j] * v;
            a3 += ps[(i0+3)*52 + j] * v;
        }
        const size_t ob = ((size_t)win*49 + i0)*CH + head*HDIM + lane;
        o[ob] = to_tf32(a0);
        if (i0+1 < 49) o[ob +   CH] = to_tf32(a1);
        if (i0+2 < 49) o[ob + 2*CH] = to_tf32(a2);
        if (i0+3 < 49) o[ob + 3*CH] = to_tf32(a3);
    }
}

// ---------------- kernel 5: LN2 ----------------
__global__ __launch_bounds__(256) void ln2_kernel(
    const float* __restrict__ x, const float* __restrict__ g, const float* __restrict__ bta,
    float* __restrict__ y)
{
    const int row = blockIdx.x;
    const int tid = threadIdx.x;
    float v = x[(size_t)row*CH + tid];
    float s = v, s2 = v*v;
    #pragma unroll
    for (int o = 16; o; o >>= 1) {
        s  += __shfl_down_sync(0xffffffffu, s,  o);
        s2 += __shfl_down_sync(0xffffffffu, s2, o);
    }
    __shared__ float ws[8], ws2[8];
    int wid = tid >> 5, lane = tid & 31;
    if (lane == 0) { ws[wid] = s; ws2[wid] = s2; }
    __syncthreads();
    if (tid == 0) {
        float ts = 0.f, ts2 = 0.f;
        #pragma unroll
        for (int i = 0; i < 8; i++) { ts += ws[i]; ts2 += ws2[i]; }
        float mu = ts * (1.f/256.f);
        ws[0] = mu;
        ws2[0] = rsqrtf(ts2*(1.f/256.f) - mu*mu + 1e-5f);
    }
    __syncthreads();
    float mu = ws[0], rstd = ws2[0];
    y[(size_t)row*CH + tid] = to_tf32((v - mu) * rstd * g[tid] + bta[tid]);
}

// ---------------- launch ----------------
extern "C" void kernel_launch(void* const* d_in, const int* in_sizes, int n_in,
                              void* d_out, int out_size)
{
    const float* x      = (const float*)d_in[0];
    const float* n1_g   = (const float*)d_in[1];
    const float* n1_b   = (const float*)d_in[2];
    const float* qkv_w  = (const float*)d_in[3];
    const float* qkv_b  = (const float*)d_in[4];
    const float* proj_w = (const float*)d_in[5];
    const float* proj_b = (const float*)d_in[6];
    const float* n2_g   = (const float*)d_in[7];
    const float* n2_b   = (const float*)d_in[8];
    const float* mlp_w1 = (const float*)d_in[9];
    const float* mlp_b1 = (const float*)d_in[10];
    const float* mlp_w2 = (const float*)d_in[11];
    const float* mlp_b2 = (const float*)d_in[12];

    float *ywin, *qkvb, *ow, *x1, *h2, *hmid;
    float *wqkv, *wproj, *w1, *w2;
    cudaGetSymbolAddress((void**)&ywin,  g_ywin);
    cudaGetSymbolAddress((void**)&qkvb,  g_qkv);
    cudaGetSymbolAddress((void**)&ow,    g_ow);
    cudaGetSymbolAddress((void**)&x1,    g_x1);
    cudaGetSymbolAddress((void**)&h2,    g_h2);
    cudaGetSymbolAddress((void**)&hmid,  g_hmid);
    cudaGetSymbolAddress((void**)&wqkv,  g_wqkv);
    cudaGetSymbolAddress((void**)&wproj, g_wproj);
    cudaGetSymbolAddress((void**)&w1,    g_w1);
    cudaGetSymbolAddress((void**)&w2,    g_w2);

    static bool attr_done = false;
    if (!attr_done) {
        cudaFuncSetAttribute(mma_gemm<EPI_BIAS>, cudaFuncAttributeMaxDynamicSharedMemorySize, SMEM_DYN);
        cudaFuncSetAttribute(mma_gemm<EPI_PROJ>, cudaFuncAttributeMaxDynamicSharedMemorySize, SMEM_DYN);
        cudaFuncSetAttribute(mma_gemm<EPI_GELU>, cudaFuncAttributeMaxDynamicSharedMemorySize, SMEM_DYN);
        cudaFuncSetAttribute(mma_gemm<EPI_RES>,  cudaFuncAttributeMaxDynamicSharedMemorySize, SMEM_DYN);
        attr_done = true;
    }

    // 0) transpose + tf32-round weights -> [N][K]
    transpose_round<<<dim3(QKVN/32,   CH/32),     256>>>(qkv_w,  wqkv,  CH,     QKVN);
    transpose_round<<<dim3(CH/32,     CH/32),     256>>>(proj_w, wproj, CH,     CH);
    transpose_round<<<dim3(HIDDEN/32, CH/32),     256>>>(mlp_w1, w1,    CH,     HIDDEN);
    transpose_round<<<dim3(CH/32,     HIDDEN/32), 256>>>(mlp_w2, w2,    HIDDEN, CH);

    // 1) LN1 + shift + window partition
    ln1_kernel<<<BATCH*98, 256>>>(x, n1_g, n1_b, ywin);

    // 2) qkv = ywin @ qkv_w + qkv_b
    mma_gemm<EPI_BIAS><<<dim3(QKVN/256, TOK/128), 256, SMEM_DYN>>>(ywin, wqkv, qkv_b, qkvb, nullptr, TOK, QKVN, CH);

    // 3) windowed attention
    attn_kernel<<<2048*HEADS, 256>>>(qkvb, ow);

    // 4) x1 = shortcut(x, NCHW) + unshift(unwindow(ow @ proj_w + proj_b))
    mma_gemm<EPI_PROJ><<<dim3(CH/256, TOK/128), 256, SMEM_DYN>>>(ow, wproj, proj_b, x1, x, TOK, CH, CH);

    // 5) h2 = LN2(x1)
    ln2_kernel<<<TOK, 256>>>(x1, n2_g, n2_b, h2);

    // 6) hmid = gelu(h2 @ mlp_w1 + mlp_b1)
    mma_gemm<EPI_GELU><<<dim3(HIDDEN/256, TOK/128), 256, SMEM_DYN>>>(h2, w1, mlp_b1, hmid, nullptr, TOK, HIDDEN, CH);

    // 7) out(NCHW) = x1 + hmid @ mlp_w2 + mlp_b2   (fused transpose)
    mma_gemm<EPI_RES><<<dim3(CH/256, TOK/128), 256, SMEM_DYN>>>(hmid, w2, mlp_b2, (float*)d_out, x1, TOK, CH, HIDDEN);
}

// round 6
// speedup vs baseline: 3.3684x; 1.1968x over previous
#include <cuda_runtime.h>
#include <cuda_fp16.h>
#include <math.h>
#include <stdint.h>

// ---------------- problem constants ----------------
#define BATCH 32
#define CH    256
#define HWS   3136
#define TOK   100352
#define SHIFT3 3
#define HEADS 8
#define HDIM  32
#define HIDDEN 1024
#define QKVN  768

// ---------------- scratch ----------------
__device__ __half g_ywin [(size_t)TOK*CH];
__device__ __half g_qkv  [(size_t)TOK*QKVN];
__device__ __half g_ow   [(size_t)TOK*CH];
__device__ float  g_x1   [(size_t)TOK*CH];
__device__ __half g_h2   [(size_t)TOK*CH];
__device__ __half g_hmid [(size_t)TOK*HIDDEN];
// fp16, TRANSPOSED weight copies: [N][K]
__device__ __half g_wqkv [QKVN*CH];
__device__ __half g_wproj[CH*CH];
__device__ __half g_w1   [HIDDEN*CH];
__device__ __half g_w2   [CH*HIDDEN];

__device__ __forceinline__ void cpasync16(uint32_t dst, const void* src) {
    asm volatile("cp.async.cg.shared.global [%0], [%1], 16;" :: "r"(dst), "l"(src));
}

// ---------------- prep: weight transpose + fp16 round ([K][N] -> [N][K]) ----------------
__global__ __launch_bounds__(256) void transpose_round(
    const float* __restrict__ w, __half* __restrict__ wt, int K, int N)
{
    __shared__ float t[32][33];
    const int k0 = blockIdx.y * 32, n0 = blockIdx.x * 32;
    const int x = threadIdx.x & 31, y = threadIdx.x >> 5;
    for (int yy = y; yy < 32; yy += 8)
        t[yy][x] = w[(size_t)(k0 + yy)*N + n0 + x];
    __syncthreads();
    for (int yy = y; yy < 32; yy += 8)
        wt[(size_t)(n0 + yy)*K + k0 + x] = __float2half_rn(t[x][yy]);
}

// ---------------- kernel 1: LN1 + shift + window partition ----------------
__global__ __launch_bounds__(256) void ln1_kernel(
    const float* __restrict__ x, const float* __restrict__ g, const float* __restrict__ bta,
    __half* __restrict__ ywin)
{
    __shared__ float ts[256*33];
    __shared__ float cmu[32], crs[32];
    const int blk = blockIdx.x;
    const int b   = blk / 98;
    const int hw0 = (blk % 98) * 32;
    const int tid = threadIdx.x;
    const float* xb = x + (size_t)b*CH*HWS;

    for (int idx = tid; idx < 256*32; idx += 256) {
        int ch = idx >> 5, j = idx & 31;
        ts[ch*33 + j] = xb[(size_t)ch*HWS + hw0 + j];
    }
    __syncthreads();

    {
        int col = tid >> 3, kk = tid & 7;
        float s = 0.f, s2 = 0.f;
        for (int ch = kk; ch < 256; ch += 8) {
            float v = ts[ch*33 + col];
            s += v; s2 += v*v;
        }
        #pragma unroll
        for (int o = 4; o; o >>= 1) {
            s  += __shfl_down_sync(0xffffffffu, s,  o, 8);
            s2 += __shfl_down_sync(0xffffffffu, s2, o, 8);
        }
        if (kk == 0) {
            float mu = s * (1.f/256.f);
            cmu[col] = mu;
            crs[col] = rsqrtf(s2*(1.f/256.f) - mu*mu + 1e-5f);
        }
    }
    __syncthreads();

    const float gg = g[tid], bb = bta[tid];
    for (int j = 0; j < 32; j++) {
        int hw = hw0 + j;
        int h = hw / 56, w = hw % 56;
        int hs = h + (56 - SHIFT3); if (hs >= 56) hs -= 56;
        int wsh = w + (56 - SHIFT3); if (wsh >= 56) wsh -= 56;
        int wi = hs / 7, r = hs % 7;
        int wj = wsh / 7, c = wsh % 7;
        int win = ((b << 3) + wi) * 8 + wj;
        int n = r*7 + c;
        ywin[((size_t)win*49 + n)*CH + tid] =
            __float2half_rn((ts[tid*33 + j] - cmu[j]) * crs[j] * gg + bb);
    }
}

// ---------------- fp16 mma GEMM: CTA 128x256, warp 64x64, ldmatrix, 4-stage ----------------
// Tiles stored [row][32 halfs] = 64B/row; 16B-chunk swizzle: c ^ ((row>>1)&3).
#define BK 32
#define STAGES 4
#define A_STAGE_B (128*64)     // bytes
#define B_STAGE_B (256*64)
#define STAGE_B   (A_STAGE_B + B_STAGE_B)
#define SMEM_DYN  (STAGES*STAGE_B)

enum { EPI_BIAS = 0, EPI_PROJ = 1, EPI_GELU = 2, EPI_RES = 3 };

__device__ __forceinline__ void ldsm4(uint32_t& r0, uint32_t& r1, uint32_t& r2, uint32_t& r3,
                                      uint32_t addr) {
    asm volatile("ldmatrix.sync.aligned.m8n8.x4.shared.b16 {%0,%1,%2,%3}, [%4];"
                 : "=r"(r0), "=r"(r1), "=r"(r2), "=r"(r3) : "r"(addr));
}

template<int EPI>
__global__ __launch_bounds__(256) void mma_gemm(
    const __half* __restrict__ A, const __half* __restrict__ BT,
    const float* __restrict__ bias, void* __restrict__ Cp,
    const float* __restrict__ aux,
    int M, int N, int K)
{
    extern __shared__ char sm[];
    const uint32_t smb = (uint32_t)__cvta_generic_to_shared(sm);

    const int tid  = threadIdx.x;
    const int lane = tid & 31, warp = tid >> 5;
    const int g    = lane >> 2, c4 = lane & 3;
    const int wm0  = (warp >> 2) * 64;
    const int wn0  = (warp & 3) * 64;
    const int m0   = blockIdx.y * 128, n0 = blockIdx.x * 256;

    // ldmatrix per-lane row mapping within a 16-row fragment
    const int fr  = ((lane >> 3) & 1) * 8 + (lane & 7);  // 0..15
    const int fk  = lane >> 4;                            // 0,1 (k 16B chunk)

    // precompute per-fragment row offsets + swizzle keys
    int arow[4], asw[4], brow[4], bsw[4];
    #pragma unroll
    for (int i = 0; i < 4; i++) {
        int ra = wm0 + i*16 + fr;
        arow[i] = ra*64; asw[i] = (ra >> 1) & 3;
        int rb = wn0 + i*16 + fr;
        brow[i] = rb*64; bsw[i] = (rb >> 1) & 3;
    }

    // cp.async mapping: thread -> (row = tid>>2 [+64..], chunk = tid&3)
    const int cr = tid >> 2, cc = tid & 3;

    float acc[4][8][4];
    #pragma unroll
    for (int i = 0; i < 4; i++)
        #pragma unroll
        for (int j = 0; j < 8; j++)
            #pragma unroll
            for (int k = 0; k < 4; k++) acc[i][j][k] = 0.f;

    auto fill = [&](int t) {
        const int s = t % STAGES;
        const uint32_t ab = smb + (uint32_t)(s*STAGE_B);
        const uint32_t bb = ab + A_STAGE_B;
        const int k0 = t * BK;
        #pragma unroll
        for (int i = 0; i < 2; i++) {
            int rr = cr + 64*i;
            cpasync16(ab + (uint32_t)(rr*64) + (uint32_t)(((cc ^ ((rr>>1)&3)))<<4),
                      &A[(size_t)(m0 + rr)*K + k0 + cc*8]);
        }
        #pragma unroll
        for (int i = 0; i < 4; i++) {
            int rr = cr + 64*i;
            cpasync16(bb + (uint32_t)(rr*64) + (uint32_t)(((cc ^ ((rr>>1)&3)))<<4),
                      &BT[(size_t)(n0 + rr)*K + k0 + cc*8]);
        }
    };

    const int nt = K / BK;
    #pragma unroll
    for (int s = 0; s < STAGES-1; s++) {
        fill(s);
        asm volatile("cp.async.commit_group;");
    }

    for (int t = 0; t < nt; t++) {
        asm volatile("cp.async.wait_group %0;" :: "n"(STAGES-2));
        __syncthreads();
        if (t + STAGES - 1 < nt) fill(t + STAGES - 1);
        asm volatile("cp.async.commit_group;");

        const uint32_t ab = smb + (uint32_t)((t % STAGES)*STAGE_B);
        const uint32_t bb = ab + A_STAGE_B;

        #pragma unroll
        for (int kk = 0; kk < 2; kk++) {
            const int kc = kk*2 + fk;
            uint32_t af[4][4], bf[4][4];
            #pragma unroll
            for (int mi = 0; mi < 4; mi++)
                ldsm4(af[mi][0], af[mi][1], af[mi][2], af[mi][3],
                      ab + (uint32_t)arow[mi] + (uint32_t)((kc ^ asw[mi]) << 4));
            #pragma unroll
            for (int np = 0; np < 4; np++)
                ldsm4(bf[np][0], bf[np][1], bf[np][2], bf[np][3],
                      bb + (uint32_t)brow[np] + (uint32_t)((kc ^ bsw[np]) << 4));

            #pragma unroll
            for (int mi = 0; mi < 4; mi++)
                #pragma unroll
                for (int ni = 0; ni < 8; ni++) {
                    const int p = ni >> 1, sb = ni & 1;
                    asm volatile(
                        "mma.sync.aligned.m16n8k16.row.col.f32.f16.f16.f32 "
                        "{%0,%1,%2,%3}, {%4,%5,%6,%7}, {%8,%9}, {%0,%1,%2,%3};"
                        : "+f"(acc[mi][ni][0]), "+f"(acc[mi][ni][1]),
                          "+f"(acc[mi][ni][2]), "+f"(acc[mi][ni][3])
                        : "r"(af[mi][0]), "r"(af[mi][1]), "r"(af[mi][2]), "r"(af[mi][3]),
                          "r"(bf[p][sb]), "r"(bf[p][2 + sb]));
                }
        }
    }

    // -------- epilogue --------
    #pragma unroll
    for (int mi = 0; mi < 4; mi++) {
        #pragma unroll
        for (int h = 0; h < 2; h++) {
            const int m = m0 + wm0 + mi*16 + g + 8*h;
            int bq = 0, sp = 0;
            if (EPI == EPI_PROJ) {
                int win = m / 49, n = m % 49;
                bq = win >> 6;
                int wr = (win >> 3) & 7;
                int wc = win & 7;
                int rr = n / 7, ccv = n % 7;
                int hh = wr*7 + rr + SHIFT3; if (hh >= 56) hh -= 56;
                int wwv = wc*7 + ccv + SHIFT3; if (wwv >= 56) wwv -= 56;
                sp = hh*56 + wwv;
            } else if (EPI == EPI_RES) {
                bq = m / HWS; sp = m % HWS;
            }
            #pragma unroll
            for (int ni = 0; ni < 8; ni++) {
                const int col = n0 + wn0 + ni*8 + 2*c4;
                float v0 = acc[mi][ni][2*h + 0] + bias[col];
                float v1 = acc[mi][ni][2*h + 1] + bias[col + 1];
                if (EPI == EPI_BIAS) {
                    __half2* C = (__half2*)Cp;
                    C[((size_t)m*N + col) >> 1] = __floats2half2_rn(v0, v1);
                } else if (EPI == EPI_PROJ) {
                    float* C = (float*)Cp;
                    size_t drow = (size_t)bq*HWS + sp;
                    float2 out;
                    out.x = v0 + aux[((size_t)(bq*CH + col    ))*HWS + sp];
                    out.y = v1 + aux[((size_t)(bq*CH + col + 1))*HWS + sp];
                    *reinterpret_cast<float2*>(&C[drow*CH + col]) = out;
                } else if (EPI == EPI_GELU) {
                    __half2* C = (__half2*)Cp;
                    float g0 = 0.5f*v0*(1.f + erff(v0*0.70710678118654752f));
                    float g1 = 0.5f*v1*(1.f + erff(v1*0.70710678118654752f));
                    C[((size_t)m*N + col) >> 1] = __floats2half2_rn(g0, g1);
                } else { // EPI_RES: residual + NCHW output
                    float* C = (float*)Cp;
                    float2 a = *reinterpret_cast<const float2*>(&aux[(size_t)m*N + col]);
                    C[((size_t)(bq*CH + col    ))*HWS + sp] = v0 + a.x;
                    C[((size_t)(bq*CH + col + 1))*HWS + sp] = v1 + a.y;
                }
            }
        }
    }
}

// ---------------- kernel 3: windowed attention (fp16 in/out, fp32 math) ----------------
__global__ __launch_bounds__(256) void attn_kernel(
    const __half* __restrict__ qkv, __half* __restrict__ o)
{
    __shared__ float qs[49*33], ks[49*33], vs[49*33];
    __shared__ float ps[52*52];
    const int win  = blockIdx.x >> 3;
    const int head = blockIdx.x & 7;
    const int tid  = threadIdx.x;
    const int w    = tid >> 5, lane = tid & 31;
    const size_t base = (size_t)win*49*QKVN + head*HDIM;

    for (int idx = tid; idx < 49*32; idx += 256) {
        int n = idx >> 5, c = idx & 31;
        size_t rb = base + (size_t)n*QKVN;
        qs[n*33 + c] = __half2float(qkv[rb + c]);
        ks[n*33 + c] = __half2float(qkv[rb + 256 + c]);
        vs[n*33 + c] = __half2float(qkv[rb + 512 + c]);
    }
    __syncthreads();

    const float scale = 0.17677669529663687f;
    const bool hasj1 = (lane + 32) < 49;

    for (int p = w; p < 25; p += 8) {
        const int i0 = 2*p;
        const int i1 = (i0 + 1 < 49) ? i0 + 1 : 48;
        float s00 = 0.f, s01 = 0.f, s10 = 0.f, s11 = 0.f;
        #pragma unroll
        for (int c = 0; c < 32; c++) {
            float q0 = qs[i0*33 + c];
            float q1 = qs[i1*33 + c];
            float k0 = ks[lane*33 + c];
            s00 += q0*k0; s10 += q1*k0;
            if (hasj1) {
                float k1 = ks[(lane+32)*33 + c];
                s01 += q0*k1; s11 += q1*k1;
            }
        }
        ps[i0*52 + lane] = s00*scale;
        if (hasj1) ps[i0*52 + lane + 32] = s01*scale;
        if (i1 != i0) {
            ps[i1*52 + lane] = s10*scale;
            if (hasj1) ps[i1*52 + lane + 32] = s11*scale;
        }
    }
    __syncthreads();

    for (int i = w; i < 49; i += 8) {
        float v0 = ps[i*52 + lane];
        float v1 = hasj1 ? ps[i*52 + lane + 32] : -1e30f;
        float mx = fmaxf(v0, v1);
        #pragma unroll
        for (int off = 16; off; off >>= 1)
            mx = fmaxf(mx, __shfl_xor_sync(0xffffffffu, mx, off));
        float e0 = __expf(v0 - mx);
        float e1 = hasj1 ? __expf(v1 - mx) : 0.f;
        float sum = e0 + e1;
        #pragma unroll
        for (int off = 16; off; off >>= 1)
            sum += __shfl_xor_sync(0xffffffffu, sum, off);
        float inv = 1.f / sum;
        ps[i*52 + lane] = e0*inv;
        if (hasj1) ps[i*52 + lane + 32] = e1*inv;
    }
    __syncthreads();

    for (int s = w; s < 13; s += 8) {
        const int i0 = 4*s;
        float a0 = 0.f, a1 = 0.f, a2 = 0.f, a3 = 0.f;
        for (int j = 0; j < 49; j++) {
            float v = vs[j*33 + lane];
            a0 += ps[(i0+0)*52 + j] * v;
            a1 += ps[(i0+1)*52 + j] * v;
            a2 += ps[(i0+2)*52 + j] * v;
            a3 += ps[(i0+3)*52 + j] * v;
        }
        const size_t ob = ((size_t)win*49 + i0)*CH + head*HDIM + lane;
        o[ob] = __float2half_rn(a0);
        if (i0+1 < 49) o[ob +   CH] = __float2half_rn(a1);
        if (i0+2 < 49) o[ob + 2*CH] = __float2half_rn(a2);
        if (i0+3 < 49) o[ob + 3*CH] = __float2half_rn(a3);
    }
}

// ---------------- kernel 5: LN2 (fp32 in, fp16 out) ----------------
__global__ __launch_bounds__(256) void ln2_kernel(
    const float* __restrict__ x, const float* __restrict__ g, const float* __restrict__ bta,
    __half* __restrict__ y)
{
    const int row = blockIdx.x;
    const int tid = threadIdx.x;
    float v = x[(size_t)row*CH + tid];
    float s = v, s2 = v*v;
    #pragma unroll
    for (int o = 16; o; o >>= 1) {
        s  += __shfl_down_sync(0xffffffffu, s,  o);
        s2 += __shfl_down_sync(0xffffffffu, s2, o);
    }
    __shared__ float ws[8], ws2[8];
    int wid = tid >> 5, lane = tid & 31;
    if (lane == 0) { ws[wid] = s; ws2[wid] = s2; }
    __syncthreads();
    if (tid == 0) {
        float ts = 0.f, ts2 = 0.f;
        #pragma unroll
        for (int i = 0; i < 8; i++) { ts += ws[i]; ts2 += ws2[i]; }
        float mu = ts * (1.f/256.f);
        ws[0] = mu;
        ws2[0] = rsqrtf(ts2*(1.f/256.f) - mu*mu + 1e-5f);
    }
    __syncthreads();
    float mu = ws[0], rstd = ws2[0];
    y[(size_t)row*CH + tid] = __float2half_rn((v - mu) * rstd * g[tid] + bta[tid]);
}

// ---------------- launch ----------------
extern "C" void kernel_launch(void* const* d_in, const int* in_sizes, int n_in,
                              void* d_out, int out_size)
{
    const float* x      = (const float*)d_in[0];
    const float* n1_g   = (const float*)d_in[1];
    const float* n1_b   = (const float*)d_in[2];
    const float* qkv_w  = (const float*)d_in[3];
    const float* qkv_b  = (const float*)d_in[4];
    const float* proj_w = (const float*)d_in[5];
    const float* proj_b = (const float*)d_in[6];
    const float* n2_g   = (const float*)d_in[7];
    const float* n2_b   = (const float*)d_in[8];
    const float* mlp_w1 = (const float*)d_in[9];
    const float* mlp_b1 = (const float*)d_in[10];
    const float* mlp_w2 = (const float*)d_in[11];
    const float* mlp_b2 = (const float*)d_in[12];

    __half *ywin, *qkvb, *ow, *h2, *hmid;
    float  *x1;
    __half *wqkv, *wproj, *w1, *w2;
    cudaGetSymbolAddress((void**)&ywin,  g_ywin);
    cudaGetSymbolAddress((void**)&qkvb,  g_qkv);
    cudaGetSymbolAddress((void**)&ow,    g_ow);
    cudaGetSymbolAddress((void**)&x1,    g_x1);
    cudaGetSymbolAddress((void**)&h2,    g_h2);
    cudaGetSymbolAddress((void**)&hmid,  g_hmid);
    cudaGetSymbolAddress((void**)&wqkv,  g_wqkv);
    cudaGetSymbolAddress((void**)&wproj, g_wproj);
    cudaGetSymbolAddress((void**)&w1,    g_w1);
    cudaGetSymbolAddress((void**)&w2,    g_w2);

    static bool attr_done = false;
    if (!attr_done) {
        cudaFuncSetAttribute(mma_gemm<EPI_BIAS>, cudaFuncAttributeMaxDynamicSharedMemorySize, SMEM_DYN);
        cudaFuncSetAttribute(mma_gemm<EPI_PROJ>, cudaFuncAttributeMaxDynamicSharedMemorySize, SMEM_DYN);
        cudaFuncSetAttribute(mma_gemm<EPI_GELU>, cudaFuncAttributeMaxDynamicSharedMemorySize, SMEM_DYN);
        cudaFuncSetAttribute(mma_gemm<EPI_RES>,  cudaFuncAttributeMaxDynamicSharedMemorySize, SMEM_DYN);
        attr_done = true;
    }

    // 0) transpose + fp16-round weights -> [N][K]
    transpose_round<<<dim3(QKVN/32,   CH/32),     256>>>(qkv_w,  wqkv,  CH,     QKVN);
    transpose_round<<<dim3(CH/32,     CH/32),     256>>>(proj_w, wproj, CH,     CH);
    transpose_round<<<dim3(HIDDEN/32, CH/32),     256>>>(mlp_w1, w1,    CH,     HIDDEN);
    transpose_round<<<dim3(CH/32,     HIDDEN/32), 256>>>(mlp_w2, w2,    HIDDEN, CH);

    // 1) LN1 + shift + window partition
    ln1_kernel<<<BATCH*98, 256>>>(x, n1_g, n1_b, ywin);

    // 2) qkv = ywin @ qkv_w + qkv_b
    mma_gemm<EPI_BIAS><<<dim3(QKVN/256, TOK/128), 256, SMEM_DYN>>>(ywin, wqkv, qkv_b, qkvb, nullptr, TOK, QKVN, CH);

    // 3) windowed attention
    attn_kernel<<<2048*HEADS, 256>>>(qkvb, ow);

    // 4) x1 = shortcut(x, NCHW) + unshift(unwindow(ow @ proj_w + proj_b))
    mma_gemm<EPI_PROJ><<<dim3(CH/256, TOK/128), 256, SMEM_DYN>>>(ow, wproj, proj_b, x1, x, TOK, CH, CH);

    // 5) h2 = LN2(x1)
    ln2_kernel<<<TOK, 256>>>(x1, n2_g, n2_b, h2);

    // 6) hmid = gelu(h2 @ mlp_w1 + mlp_b1)
    mma_gemm<EPI_GELU><<<dim3(HIDDEN/256, TOK/128), 256, SMEM_DYN>>>(h2, w1, mlp_b1, hmid, nullptr, TOK, HIDDEN, CH);

    // 7) out(NCHW) = x1 + hmid @ mlp_w2 + mlp_b2   (fused transpose)
    mma_gemm<EPI_RES><<<dim3(CH/256, TOK/128), 256, SMEM_DYN>>>(hmid, w2, mlp_b2, (float*)d_out, x1, TOK, CH, HIDDEN);
}

// round 7
// speedup vs baseline: 4.0790x; 1.2110x over previous
#include <cuda_runtime.h>
#include <cuda_fp16.h>
#include <math.h>
#include <stdint.h>

// ---------------- problem constants ----------------
#define BATCH 32
#define CH    256
#define HWS   3136
#define TOK   100352
#define SHIFT3 3
#define HEADS 8
#define HDIM  32
#define HIDDEN 1024
#define QKVN  768

// ---------------- scratch ----------------
__device__ __half g_ywin [(size_t)TOK*CH];
__device__ __half g_qkv  [(size_t)TOK*QKVN];
__device__ __half g_ow   [(size_t)TOK*CH];
__device__ float  g_x1   [(size_t)TOK*CH];
__device__ __half g_h2   [(size_t)TOK*CH];
__device__ __half g_hmid [(size_t)TOK*HIDDEN];
// fp16, TRANSPOSED weight copies: [N][K]
__device__ __half g_wqkv [QKVN*CH];
__device__ __half g_wproj[CH*CH];
__device__ __half g_w1   [HIDDEN*CH];
__device__ __half g_w2   [CH*HIDDEN];

__device__ __forceinline__ void cpasync16(uint32_t dst, const void* src) {
    asm volatile("cp.async.cg.shared.global [%0], [%1], 16;" :: "r"(dst), "l"(src));
}

__device__ __forceinline__ void ldsm4(uint32_t& r0, uint32_t& r1, uint32_t& r2, uint32_t& r3,
                                      uint32_t addr) {
    asm volatile("ldmatrix.sync.aligned.m8n8.x4.shared.b16 {%0,%1,%2,%3}, [%4];"
                 : "=r"(r0), "=r"(r1), "=r"(r2), "=r"(r3) : "r"(addr));
}

#define MMA16816(d0,d1,d2,d3,a0,a1,a2,a3,b0,b1) \
    asm volatile( \
        "mma.sync.aligned.m16n8k16.row.col.f32.f16.f16.f32 " \
        "{%0,%1,%2,%3}, {%4,%5,%6,%7}, {%8,%9}, {%0,%1,%2,%3};" \
        : "+f"(d0), "+f"(d1), "+f"(d2), "+f"(d3) \
        : "r"(a0), "r"(a1), "r"(a2), "r"(a3), "r"(b0), "r"(b1))

// ---------------- prep: weight transpose + fp16 round ([K][N] -> [N][K]) ----------------
__global__ __launch_bounds__(256) void transpose_round(
    const float* __restrict__ w, __half* __restrict__ wt, int K, int N)
{
    __shared__ float t[32][33];
    const int k0 = blockIdx.y * 32, n0 = blockIdx.x * 32;
    const int x = threadIdx.x & 31, y = threadIdx.x >> 5;
    for (int yy = y; yy < 32; yy += 8)
        t[yy][x] = w[(size_t)(k0 + yy)*N + n0 + x];
    __syncthreads();
    for (int yy = y; yy < 32; yy += 8)
        wt[(size_t)(n0 + yy)*K + k0 + x] = __float2half_rn(t[x][yy]);
}

// ---------------- kernel 1: LN1 + shift + window partition ----------------
__global__ __launch_bounds__(256) void ln1_kernel(
    const float* __restrict__ x, const float* __restrict__ g, const float* __restrict__ bta,
    __half* __restrict__ ywin)
{
    __shared__ float ts[256*33];
    __shared__ float cmu[32], crs[32];
    const int blk = blockIdx.x;
    const int b   = blk / 98;
    const int hw0 = (blk % 98) * 32;
    const int tid = threadIdx.x;
    const float* xb = x + (size_t)b*CH*HWS;

    for (int idx = tid; idx < 256*32; idx += 256) {
        int ch = idx >> 5, j = idx & 31;
        ts[ch*33 + j] = xb[(size_t)ch*HWS + hw0 + j];
    }
    __syncthreads();

    {
        int col = tid >> 3, kk = tid & 7;
        float s = 0.f, s2 = 0.f;
        for (int ch = kk; ch < 256; ch += 8) {
            float v = ts[ch*33 + col];
            s += v; s2 += v*v;
        }
        #pragma unroll
        for (int o = 4; o; o >>= 1) {
            s  += __shfl_down_sync(0xffffffffu, s,  o, 8);
            s2 += __shfl_down_sync(0xffffffffu, s2, o, 8);
        }
        if (kk == 0) {
            float mu = s * (1.f/256.f);
            cmu[col] = mu;
            crs[col] = rsqrtf(s2*(1.f/256.f) - mu*mu + 1e-5f);
        }
    }
    __syncthreads();

    const float gg = g[tid], bb = bta[tid];
    for (int j = 0; j < 32; j++) {
        int hw = hw0 + j;
        int h = hw / 56, w = hw % 56;
        int hs = h + (56 - SHIFT3); if (hs >= 56) hs -= 56;
        int wsh = w + (56 - SHIFT3); if (wsh >= 56) wsh -= 56;
        int wi = hs / 7, r = hs % 7;
        int wj = wsh / 7, c = wsh % 7;
        int win = ((b << 3) + wi) * 8 + wj;
        int n = r*7 + c;
        ywin[((size_t)win*49 + n)*CH + tid] =
            __float2half_rn((ts[tid*33 + j] - cmu[j]) * crs[j] * gg + bb);
    }
}

// ---------------- fp16 mma GEMM: CTA 128x256, warp 64x64, ldmatrix, 4-stage ----------------
#define BK 32
#define STAGES 4
#define A_STAGE_B (128*64)
#define B_STAGE_B (256*64)
#define STAGE_B   (A_STAGE_B + B_STAGE_B)
#define SMEM_DYN  (STAGES*STAGE_B)

enum { EPI_BIAS = 0, EPI_PROJLN = 1, EPI_GELU = 2, EPI_RES = 3 };

template<int EPI>
__global__ __launch_bounds__(256) void mma_gemm(
    const __half* __restrict__ A, const __half* __restrict__ BT,
    const float* __restrict__ bias, void* __restrict__ Cp,
    const float* __restrict__ aux,
    const float* __restrict__ gamma, const float* __restrict__ beta2,
    __half* __restrict__ h2out,
    int M, int N, int K)
{
    extern __shared__ char sm[];
    const uint32_t smb = (uint32_t)__cvta_generic_to_shared(sm);

    const int tid  = threadIdx.x;
    const int lane = tid & 31, warp = tid >> 5;
    const int g    = lane >> 2, c4 = lane & 3;
    const int wm0  = (warp >> 2) * 64;
    const int wn0  = (warp & 3) * 64;
    const int m0   = blockIdx.y * 128, n0 = blockIdx.x * 256;

    const int fr  = ((lane >> 3) & 1) * 8 + (lane & 7);
    const int fk  = lane >> 4;

    int arow[4], asw[4], brow[4], bsw[4];
    #pragma unroll
    for (int i = 0; i < 4; i++) {
        int ra = wm0 + i*16 + fr;
        arow[i] = ra*64; asw[i] = (ra >> 1) & 3;
        int rb = wn0 + i*16 + fr;
        brow[i] = rb*64; bsw[i] = (rb >> 1) & 3;
    }

    const int cr = tid >> 2, cc = tid & 3;

    float acc[4][8][4];
    #pragma unroll
    for (int i = 0; i < 4; i++)
        #pragma unroll
        for (int j = 0; j < 8; j++)
            #pragma unroll
            for (int k = 0; k < 4; k++) acc[i][j][k] = 0.f;

    auto fill = [&](int t) {
        const int s = t % STAGES;
        const uint32_t ab = smb + (uint32_t)(s*STAGE_B);
        const uint32_t bb = ab + A_STAGE_B;
        const int k0 = t * BK;
        #pragma unroll
        for (int i = 0; i < 2; i++) {
            int rr = cr + 64*i;
            cpasync16(ab + (uint32_t)(rr*64) + (uint32_t)(((cc ^ ((rr>>1)&3)))<<4),
                      &A[(size_t)(m0 + rr)*K + k0 + cc*8]);
        }
        #pragma unroll
        for (int i = 0; i < 4; i++) {
            int rr = cr + 64*i;
            cpasync16(bb + (uint32_t)(rr*64) + (uint32_t)(((cc ^ ((rr>>1)&3)))<<4),
                      &BT[(size_t)(n0 + rr)*K + k0 + cc*8]);
        }
    };

    const int nt = K / BK;
    #pragma unroll
    for (int s = 0; s < STAGES-1; s++) {
        fill(s);
        asm volatile("cp.async.commit_group;");
    }

    for (int t = 0; t < nt; t++) {
        asm volatile("cp.async.wait_group %0;" :: "n"(STAGES-2));
        __syncthreads();
        if (t + STAGES - 1 < nt) fill(t + STAGES - 1);
        asm volatile("cp.async.commit_group;");

        const uint32_t ab = smb + (uint32_t)((t % STAGES)*STAGE_B);
        const uint32_t bb = ab + A_STAGE_B;

        #pragma unroll
        for (int kk = 0; kk < 2; kk++) {
            const int kc = kk*2 + fk;
            uint32_t af[4][4], bf[4][4];
            #pragma unroll
            for (int mi = 0; mi < 4; mi++)
                ldsm4(af[mi][0], af[mi][1], af[mi][2], af[mi][3],
                      ab + (uint32_t)arow[mi] + (uint32_t)((kc ^ asw[mi]) << 4));
            #pragma unroll
            for (int np = 0; np < 4; np++)
                ldsm4(bf[np][0], bf[np][1], bf[np][2], bf[np][3],
                      bb + (uint32_t)brow[np] + (uint32_t)((kc ^ bsw[np]) << 4));

            #pragma unroll
            for (int mi = 0; mi < 4; mi++)
                #pragma unroll
                for (int ni = 0; ni < 8; ni++) {
                    const int p = ni >> 1, sb = ni & 1;
                    MMA16816(acc[mi][ni][0], acc[mi][ni][1], acc[mi][ni][2], acc[mi][ni][3],
                             af[mi][0], af[mi][1], af[mi][2], af[mi][3],
                             bf[p][sb], bf[p][2 + sb]);
                }
        }
    }

    // -------- epilogue --------
    if (EPI == EPI_PROJLN) {
        // finalize x1 = proj + bias + shortcut into acc; write x1; fused LN2 -> h2
        asm volatile("cp.async.wait_group 0;" ::: "memory");
        __syncthreads();
        float* red  = (float*)sm;          // [128][4]
        float* red2 = red + 512;           // [128][4]
        float* smu  = red2 + 512;          // [128]
        float* srs  = smu + 128;           // [128]

        float* C = (float*)Cp;
        float psum[4][2], psum2[4][2];
        #pragma unroll
        for (int mi = 0; mi < 4; mi++) { psum[mi][0]=psum[mi][1]=psum2[mi][0]=psum2[mi][1]=0.f; }

        #pragma unroll
        for (int mi = 0; mi < 4; mi++) {
            #pragma unroll
            for (int h = 0; h < 2; h++) {
                const int m = m0 + wm0 + mi*16 + g + 8*h;
                int win = m / 49, n = m % 49;
                int bq = win >> 6;
                int wr = (win >> 3) & 7;
                int wc = win & 7;
                int rr = n / 7, ccv = n % 7;
                int hh = wr*7 + rr + SHIFT3; if (hh >= 56) hh -= 56;
                int wwv = wc*7 + ccv + SHIFT3; if (wwv >= 56) wwv -= 56;
                int sp = hh*56 + wwv;
                size_t drow = (size_t)bq*HWS + sp;
                #pragma unroll
                for (int ni = 0; ni < 8; ni++) {
                    const int col = wn0 + ni*8 + 2*c4;
                    float v0 = acc[mi][ni][2*h+0] + bias[col] + aux[((size_t)(bq*CH + col    ))*HWS + sp];
                    float v1 = acc[mi][ni][2*h+1] + bias[col+1] + aux[((size_t)(bq*CH + col + 1))*HWS + sp];
                    acc[mi][ni][2*h+0] = v0; acc[mi][ni][2*h+1] = v1;
                    float2 out; out.x = v0; out.y = v1;
                    *reinterpret_cast<float2*>(&C[drow*CH + col]) = out;
                    psum [mi][h] += v0 + v1;
                    psum2[mi][h] += v0*v0 + v1*v1;
                }
            }
        }
        #pragma unroll
        for (int mi = 0; mi < 4; mi++)
            #pragma unroll
            for (int h = 0; h < 2; h++) {
                float s = psum[mi][h], s2 = psum2[mi][h];
                s  += __shfl_xor_sync(0xffffffffu, s, 1);  s  += __shfl_xor_sync(0xffffffffu, s, 2);
                s2 += __shfl_xor_sync(0xffffffffu, s2, 1); s2 += __shfl_xor_sync(0xffffffffu, s2, 2);
                if (c4 == 0) {
                    int rloc = wm0 + mi*16 + g + 8*h;
                    red [rloc*4 + (warp & 3)] = s;
                    red2[rloc*4 + (warp & 3)] = s2;
                }
            }
        __syncthreads();
        if (tid < 128) {
            float s  = red [tid*4] + red [tid*4+1] + red [tid*4+2] + red [tid*4+3];
            float s2 = red2[tid*4] + red2[tid*4+1] + red2[tid*4+2] + red2[tid*4+3];
            float mu = s * (1.f/256.f);
            smu[tid] = mu;
            srs[tid] = rsqrtf(s2*(1.f/256.f) - mu*mu + 1e-5f);
        }
        __syncthreads();
        #pragma unroll
        for (int mi = 0; mi < 4; mi++) {
            #pragma unroll
            for (int h = 0; h < 2; h++) {
                const int rloc = wm0 + mi*16 + g + 8*h;
                const int m = m0 + rloc;
                float mu = smu[rloc], rs = srs[rloc];
                int win = m / 49, n = m % 49;
                int bq = win >> 6;
                int wr = (win >> 3) & 7;
                int wc = win & 7;
                int rr = n / 7, ccv = n % 7;
                int hh = wr*7 + rr + SHIFT3; if (hh >= 56) hh -= 56;
                int wwv = wc*7 + ccv + SHIFT3; if (wwv >= 56) wwv -= 56;
                size_t drow = (size_t)bq*HWS + hh*56 + wwv;
                #pragma unroll
                for (int ni = 0; ni < 8; ni++) {
                    const int col = wn0 + ni*8 + 2*c4;
                    float h0 = (acc[mi][ni][2*h+0] - mu)*rs*gamma[col  ] + beta2[col  ];
                    float h1 = (acc[mi][ni][2*h+1] - mu)*rs*gamma[col+1] + beta2[col+1];
                    *reinterpret_cast<__half2*>(&h2out[drow*CH + col]) = __floats2half2_rn(h0, h1);
                }
            }
        }
        return;
    }

    #pragma unroll
    for (int mi = 0; mi < 4; mi++) {
        #pragma unroll
        for (int h = 0; h < 2; h++) {
            const int m = m0 + wm0 + mi*16 + g + 8*h;
            int bq = 0, sp = 0;
            if (EPI == EPI_RES) { bq = m / HWS; sp = m % HWS; }
            #pragma unroll
            for (int ni = 0; ni < 8; ni++) {
                const int col = n0 + wn0 + ni*8 + 2*c4;
                float v0 = acc[mi][ni][2*h + 0] + bias[col];
                float v1 = acc[mi][ni][2*h + 1] + bias[col + 1];
                if (EPI == EPI_BIAS) {
                    __half2* C = (__half2*)Cp;
                    C[((size_t)m*N + col) >> 1] = __floats2half2_rn(v0, v1);
                } else if (EPI == EPI_GELU) {
                    __half2* C = (__half2*)Cp;
                    float g0 = 0.5f*v0*(1.f + erff(v0*0.70710678118654752f));
                    float g1 = 0.5f*v1*(1.f + erff(v1*0.70710678118654752f));
                    C[((size_t)m*N + col) >> 1] = __floats2half2_rn(g0, g1);
                } else { // EPI_RES
                    float* C = (float*)Cp;
                    float2 a = *reinterpret_cast<const float2*>(&aux[(size_t)m*N + col]);
                    C[((size_t)(bq*CH + col    ))*HWS + sp] = v0 + a.x;
                    C[((size_t)(bq*CH + col + 1))*HWS + sp] = v1 + a.y;
                }
            }
        }
    }
}

// ---------------- kernel 3: tensor-core windowed attention ----------------
// block = 1 window, warp = 1 head. Q/K: 64 rows x 40 halfs (80B stride).
// V^T: 32 rows x 72 halfs (144B stride). All zero-padded.
#define QK_STRIDE 40
#define VT_STRIDE 72
#define QH_HALFS  (64*QK_STRIDE)   // 2560
#define VH_HALFS  (32*VT_STRIDE)   // 2304
#define ATT_SMEM  ((16*QH_HALFS + 8*VH_HALFS)*2)   // 118784 B

__global__ __launch_bounds__(256) void attn_kernel(
    const __half* __restrict__ qkv, __half* __restrict__ o)
{
    extern __shared__ __half ash[];
    const int win  = blockIdx.x;
    const int tid  = threadIdx.x;
    const int head = tid >> 5, lane = tid & 31;
    const int g    = lane >> 2, c4 = lane & 3;
    const int fr   = ((lane >> 3) & 1) * 8 + (lane & 7);
    const int fk   = lane >> 4;

    __half* Qb = ash;
    __half* Kb = ash + 8*QH_HALFS;
    __half* Vb = ash + 16*QH_HALFS;

    // zero-init all tiles
    for (int i = tid; i < (16*QH_HALFS + 8*VH_HALFS)/8; i += 256)
        ((uint4*)ash)[i] = make_uint4(0,0,0,0);
    __syncthreads();

    // load q,k,v: 49 rows x 96 16B-chunks
    const __half* src = qkv + (size_t)win*49*QKVN;
    for (int idx = tid; idx < 49*96; idx += 256) {
        int n = idx / 96, ck = idx % 96;
        int sec = ck >> 5;
        int cc  = ck & 31;
        int h   = cc >> 2, dq = (cc & 3)*8;
        uint4 v = *(const uint4*)(src + (size_t)n*QKVN + ck*8);
        if (sec == 0)      *(uint4*)(Qb + h*QH_HALFS + n*QK_STRIDE + dq) = v;
        else if (sec == 1) *(uint4*)(Kb + h*QH_HALFS + n*QK_STRIDE + dq) = v;
        else {
            __half tmp[8]; *(uint4*)tmp = v;
            #pragma unroll
            for (int e = 0; e < 8; e++)
                Vb[h*VH_HALFS + (dq + e)*VT_STRIDE + n] = tmp[e];
        }
    }
    __syncthreads();

    const uint32_t Qsm = (uint32_t)__cvta_generic_to_shared(Qb + head*QH_HALFS) + fr*QK_STRIDE*2;
    const uint32_t Ksm = (uint32_t)__cvta_generic_to_shared(Kb + head*QH_HALFS) + fr*QK_STRIDE*2;
    const uint32_t Vsm = (uint32_t)__cvta_generic_to_shared(Vb + head*VH_HALFS) + fr*VT_STRIDE*2;

    // ---- S = Q K^T ----
    float acc[4][7][4];
    #pragma unroll
    for (int i = 0; i < 4; i++)
        #pragma unroll
        for (int j = 0; j < 7; j++)
            #pragma unroll
            for (int k = 0; k < 4; k++) acc[i][j][k] = 0.f;

    #pragma unroll
    for (int kk = 0; kk < 2; kk++) {
        const int kc = kk*2 + fk;
        uint32_t af[4][4], bf[4][4];
        #pragma unroll
        for (int mi = 0; mi < 4; mi++)
            ldsm4(af[mi][0], af[mi][1], af[mi][2], af[mi][3],
                  Qsm + mi*16*QK_STRIDE*2 + kc*16);
        #pragma unroll
        for (int p = 0; p < 4; p++)
            ldsm4(bf[p][0], bf[p][1], bf[p][2], bf[p][3],
                  Ksm + p*16*QK_STRIDE*2 + kc*16);
        #pragma unroll
        for (int mi = 0; mi < 4; mi++)
            #pragma unroll
            for (int ni = 0; ni < 7; ni++) {
                const int p = ni >> 1, sb = ni & 1;
                MMA16816(acc[mi][ni][0], acc[mi][ni][1], acc[mi][ni][2], acc[mi][ni][3],
                         af[mi][0], af[mi][1], af[mi][2], af[mi][3],
                         bf[p][sb], bf[p][2 + sb]);
            }
    }

    // ---- softmax (register, per-row; row held by 4 lanes c4=0..3) ----
    const float scale = 0.17677669529663687f;
    float mx[4][2], sum[4][2];
    #pragma unroll
    for (int mi = 0; mi < 4; mi++) { mx[mi][0] = mx[mi][1] = -1e30f; sum[mi][0] = sum[mi][1] = 0.f; }

    #pragma unroll
    for (int mi = 0; mi < 4; mi++)
        #pragma unroll
        for (int ni = 0; ni < 7; ni++)
            #pragma unroll
            for (int b = 0; b < 2; b++) {
                int j = ni*8 + 2*c4 + b;
                float v0 = acc[mi][ni][b]   * scale;
                float v1 = acc[mi][ni][2+b] * scale;
                if (j >= 49) { v0 = -1e30f; v1 = -1e30f; }
                acc[mi][ni][b] = v0; acc[mi][ni][2+b] = v1;
                mx[mi][0] = fmaxf(mx[mi][0], v0);
                mx[mi][1] = fmaxf(mx[mi][1], v1);
            }
    #pragma unroll
    for (int mi = 0; mi < 4; mi++)
        #pragma unroll
        for (int r = 0; r < 2; r++) {
            float m_ = mx[mi][r];
            m_ = fmaxf(m_, __shfl_xor_sync(0xffffffffu, m_, 1));
            m_ = fmaxf(m_, __shfl_xor_sync(0xffffffffu, m_, 2));
            mx[mi][r] = m_;
        }
    #pragma unroll
    for (int mi = 0; mi < 4; mi++)
        #pragma unroll
        for (int ni = 0; ni < 7; ni++)
            #pragma unroll
            for (int b = 0; b < 2; b++) {
                float e0 = __expf(acc[mi][ni][b]   - mx[mi][0]);
                float e1 = __expf(acc[mi][ni][2+b] - mx[mi][1]);
                acc[mi][ni][b] = e0; acc[mi][ni][2+b] = e1;
                sum[mi][0] += e0; sum[mi][1] += e1;
            }
    #pragma unroll
    for (int mi = 0; mi < 4; mi++)
        #pragma unroll
        for (int r = 0; r < 2; r++) {
            float s_ = sum[mi][r];
            s_ += __shfl_xor_sync(0xffffffffu, s_, 1);
            s_ += __shfl_xor_sync(0xffffffffu, s_, 2);
            sum[mi][r] = 1.f / s_;
        }

    // pack P to half2 fragments (frees fp32 regs)
    uint32_t ph[4][7][2];
    #pragma unroll
    for (int mi = 0; mi < 4; mi++)
        #pragma unroll
        for (int ni = 0; ni < 7; ni++) {
            __half2 p0 = __floats2half2_rn(acc[mi][ni][0]*sum[mi][0], acc[mi][ni][1]*sum[mi][0]);
            __half2 p1 = __floats2half2_rn(acc[mi][ni][2]*sum[mi][1], acc[mi][ni][3]*sum[mi][1]);
            ph[mi][ni][0] = *reinterpret_cast<uint32_t*>(&p0);
            ph[mi][ni][1] = *reinterpret_cast<uint32_t*>(&p1);
        }

    // ---- O = P V ----
    float oacc[4][4][4];
    #pragma unroll
    for (int i = 0; i < 4; i++)
        #pragma unroll
        for (int j = 0; j < 4; j++)
            #pragma unroll
            for (int k = 0; k < 4; k++) oacc[i][j][k] = 0.f;

    #pragma unroll
    for (int kf = 0; kf < 4; kf++) {
        const int chunk = 2*kf + fk;
        uint32_t bf[2][4];
        #pragma unroll
        for (int p = 0; p < 2; p++)
            ldsm4(bf[p][0], bf[p][1], bf[p][2], bf[p][3],
                  Vsm + p*16*VT_STRIDE*2 + chunk*16);
        #pragma unroll
        for (int mi = 0; mi < 4; mi++) {
            const int n0f = 2*kf, n1f = 2*kf + 1;
            uint32_t a0 = ph[mi][n0f][0], a1 = ph[mi][n0f][1];
            uint32_t a2 = (n1f < 7) ? ph[mi][n1f][0] : 0u;
            uint32_t a3 = (n1f < 7) ? ph[mi][n1f][1] : 0u;
            #pragma unroll
            for (int ni2 = 0; ni2 < 4; ni2++) {
                const int p = ni2 >> 1, sb = ni2 & 1;
                MMA16816(oacc[mi][ni2][0], oacc[mi][ni2][1], oacc[mi][ni2][2], oacc[mi][ni2][3],
                         a0, a1, a2, a3, bf[p][sb], bf[p][2 + sb]);
            }
        }
    }

    // ---- store O ----
    #pragma unroll
    for (int mi = 0; mi < 4; mi++) {
        const int i0 = mi*16 + g, i1 = i0 + 8;
        #pragma unroll
        for (int ni2 = 0; ni2 < 4; ni2++) {
            const int col = head*HDIM + ni2*8 + 2*c4;
            if (i0 < 49) {
                __half2 v = __floats2half2_rn(oacc[mi][ni2][0], oacc[mi][ni2][1]);
                *reinterpret_cast<__half2*>(&o[((size_t)win*49 + i0)*CH + col]) = v;
            }
            if (i1 < 49) {
                __half2 v = __floats2half2_rn(oacc[mi][ni2][2], oacc[mi][ni2][3]);
                *reinterpret_cast<__half2*>(&o[((size_t)win*49 + i1)*CH + col]) = v;
            }
        }
    }
}

// ---------------- launch ----------------
extern "C" void kernel_launch(void* const* d_in, const int* in_sizes, int n_in,
                              void* d_out, int out_size)
{
    const float* x      = (const float*)d_in[0];
    const float* n1_g   = (const float*)d_in[1];
    const float* n1_b   = (const float*)d_in[2];
    const float* qkv_w  = (const float*)d_in[3];
    const float* qkv_b  = (const float*)d_in[4];
    const float* proj_w = (const float*)d_in[5];
    const float* proj_b = (const float*)d_in[6];
    const float* n2_g   = (const float*)d_in[7];
    const float* n2_b   = (const float*)d_in[8];
    const float* mlp_w1 = (const float*)d_in[9];
    const float* mlp_b1 = (const float*)d_in[10];
    const float* mlp_w2 = (const float*)d_in[11];
    const float* mlp_b2 = (const float*)d_in[12];

    __half *ywin, *qkvb, *ow, *h2, *hmid;
    float  *x1;
    __half *wqkv, *wproj, *w1, *w2;
    cudaGetSymbolAddress((void**)&ywin,  g_ywin);
    cudaGetSymbolAddress((void**)&qkvb,  g_qkv);
    cudaGetSymbolAddress((void**)&ow,    g_ow);
    cudaGetSymbolAddress((void**)&x1,    g_x1);
    cudaGetSymbolAddress((void**)&h2,    g_h2);
    cudaGetSymbolAddress((void**)&hmid,  g_hmid);
    cudaGetSymbolAddress((void**)&wqkv,  g_wqkv);
    cudaGetSymbolAddress((void**)&wproj, g_wproj);
    cudaGetSymbolAddress((void**)&w1,    g_w1);
    cudaGetSymbolAddress((void**)&w2,    g_w2);

    static bool attr_done = false;
    if (!attr_done) {
        cudaFuncSetAttribute(mma_gemm<EPI_BIAS>,   cudaFuncAttributeMaxDynamicSharedMemorySize, SMEM_DYN);
        cudaFuncSetAttribute(mma_gemm<EPI_PROJLN>, cudaFuncAttributeMaxDynamicSharedMemorySize, SMEM_DYN);
        cudaFuncSetAttribute(mma_gemm<EPI_GELU>,   cudaFuncAttributeMaxDynamicSharedMemorySize, SMEM_DYN);
        cudaFuncSetAttribute(mma_gemm<EPI_RES>,    cudaFuncAttributeMaxDynamicSharedMemorySize, SMEM_DYN);
        cudaFuncSetAttribute(attn_kernel,          cudaFuncAttributeMaxDynamicSharedMemorySize, ATT_SMEM);
        attr_done = true;
    }

    // 0) transpose + fp16-round weights -> [N][K]
    transpose_round<<<dim3(QKVN/32,   CH/32),     256>>>(qkv_w,  wqkv,  CH,     QKVN);
    transpose_round<<<dim3(CH/32,     CH/32),     256>>>(proj_w, wproj, CH,     CH);
    transpose_round<<<dim3(HIDDEN/32, CH/32),     256>>>(mlp_w1, w1,    CH,     HIDDEN);
    transpose_round<<<dim3(CH/32,     HIDDEN/32), 256>>>(mlp_w2, w2,    HIDDEN, CH);

    // 1) LN1 + shift + window partition
    ln1_kernel<<<BATCH*98, 256>>>(x, n1_g, n1_b, ywin);

    // 2) qkv = ywin @ qkv_w + qkv_b
    mma_gemm<EPI_BIAS><<<dim3(QKVN/256, TOK/128), 256, SMEM_DYN>>>(
        ywin, wqkv, qkv_b, qkvb, nullptr, nullptr, nullptr, nullptr, TOK, QKVN, CH);

    // 3) tensor-core windowed attention
    attn_kernel<<<2048, 256, ATT_SMEM>>>(qkvb, ow);

    // 4) x1 = shortcut(x) + proj(ow); h2 = LN2(x1)   (fused)
    mma_gemm<EPI_PROJLN><<<dim3(CH/256, TOK/128), 256, SMEM_DYN>>>(
        ow, wproj, proj_b, x1, x, n2_g, n2_b, h2, TOK, CH, CH);

    // 5) hmid = gelu(h2 @ mlp_w1 + mlp_b1)
    mma_gemm<EPI_GELU><<<dim3(HIDDEN/256, TOK/128), 256, SMEM_DYN>>>(
        h2, w1, mlp_b1, hmid, nullptr, nullptr, nullptr, nullptr, TOK, HIDDEN, CH);

    // 6) out(NCHW) = x1 + hmid @ mlp_w2 + mlp_b2   (fused transpose)
    mma_gemm<EPI_RES><<<dim3(CH/256, TOK/128), 256, SMEM_DYN>>>(
        hmid, w2, mlp_b2, (float*)d_out, x1, nullptr, nullptr, nullptr, TOK, CH, HIDDEN);
}

// round 8
// speedup vs baseline: 4.2419x; 1.0399x over previous
#include <cuda_runtime.h>
#include <cuda_fp16.h>
#include <math.h>
#include <stdint.h>

// ---------------- problem constants ----------------
#define BATCH 32
#define CH    256
#define HWS   3136
#define TOK   100352
#define SHIFT3 3
#define HEADS 8
#define HDIM  32
#define HIDDEN 1024
#define QKVN  768

// ---------------- scratch ----------------
__device__ __half g_ywin [(size_t)TOK*CH];
__device__ __half g_qkv  [(size_t)TOK*QKVN];
__device__ __half g_ow   [(size_t)TOK*CH];
__device__ float  g_x1   [(size_t)TOK*CH];
__device__ __half g_h2   [(size_t)TOK*CH];
__device__ __half g_hmid [(size_t)TOK*HIDDEN];
// fp16, TRANSPOSED weight copies: [N][K]
__device__ __half g_wqkv [QKVN*CH];
__device__ __half g_wproj[CH*CH];
__device__ __half g_w1   [HIDDEN*CH];
__device__ __half g_w2   [CH*HIDDEN];

__device__ __forceinline__ void cpasync16(uint32_t dst, const void* src) {
    asm volatile("cp.async.cg.shared.global [%0], [%1], 16;" :: "r"(dst), "l"(src));
}

__device__ __forceinline__ void ldsm4(uint32_t& r0, uint32_t& r1, uint32_t& r2, uint32_t& r3,
                                      uint32_t addr) {
    asm volatile("ldmatrix.sync.aligned.m8n8.x4.shared.b16 {%0,%1,%2,%3}, [%4];"
                 : "=r"(r0), "=r"(r1), "=r"(r2), "=r"(r3) : "r"(addr));
}

#define MMA16816(d0,d1,d2,d3,a0,a1,a2,a3,b0,b1) \
    asm volatile( \
        "mma.sync.aligned.m16n8k16.row.col.f32.f16.f16.f32 " \
        "{%0,%1,%2,%3}, {%4,%5,%6,%7}, {%8,%9}, {%0,%1,%2,%3};" \
        : "+f"(d0), "+f"(d1), "+f"(d2), "+f"(d3) \
        : "r"(a0), "r"(a1), "r"(a2), "r"(a3), "r"(b0), "r"(b1))

// ---------------- prep: ALL weights transpose + fp16 round, one launch ----------------
// segments: 0: qkv (K=256,N=768,192 blk) 1: proj (64) 2: w1 (256) 3: w2 (256)
__global__ __launch_bounds__(256) void transpose_round_all(
    const float* __restrict__ w0, __half* __restrict__ o0,
    const float* __restrict__ w1_, __half* __restrict__ o1,
    const float* __restrict__ w2_, __half* __restrict__ o2,
    const float* __restrict__ w3_, __half* __restrict__ o3)
{
    __shared__ float t[32][33];
    int blk = blockIdx.x;
    const float* w; __half* wt; int K, N, nb;
    if (blk < 192)      { w = w0;  wt = o0; K = CH;     N = QKVN;   nb = QKVN/32; }
    else if (blk < 256) { blk -= 192; w = w1_; wt = o1; K = CH;     N = CH;     nb = CH/32; }
    else if (blk < 512) { blk -= 256; w = w2_; wt = o2; K = CH;     N = HIDDEN; nb = HIDDEN/32; }
    else                { blk -= 512; w = w3_; wt = o3; K = HIDDEN; N = CH;     nb = CH/32; }
    const int k0 = (blk / nb) * 32, n0 = (blk % nb) * 32;
    const int x = threadIdx.x & 31, y = threadIdx.x >> 5;
    for (int yy = y; yy < 32; yy += 8)
        t[yy][x] = w[(size_t)(k0 + yy)*N + n0 + x];
    __syncthreads();
    for (int yy = y; yy < 32; yy += 8)
        wt[(size_t)(n0 + yy)*K + k0 + x] = __float2half_rn(t[x][yy]);
}

// ---------------- kernel 1: LN1 + shift + window partition ----------------
__global__ __launch_bounds__(256) void ln1_kernel(
    const float* __restrict__ x, const float* __restrict__ g, const float* __restrict__ bta,
    __half* __restrict__ ywin)
{
    __shared__ float ts[256*33];
    __shared__ float cmu[32], crs[32];
    const int blk = blockIdx.x;
    const int b   = blk / 98;
    const int hw0 = (blk % 98) * 32;
    const int tid = threadIdx.x;
    const float* xb = x + (size_t)b*CH*HWS;

    for (int idx = tid; idx < 256*32; idx += 256) {
        int ch = idx >> 5, j = idx & 31;
        ts[ch*33 + j] = xb[(size_t)ch*HWS + hw0 + j];
    }
    __syncthreads();

    {
        int col = tid >> 3, kk = tid & 7;
        float s = 0.f, s2 = 0.f;
        for (int ch = kk; ch < 256; ch += 8) {
            float v = ts[ch*33 + col];
            s += v; s2 += v*v;
        }
        #pragma unroll
        for (int o = 4; o; o >>= 1) {
            s  += __shfl_down_sync(0xffffffffu, s,  o, 8);
            s2 += __shfl_down_sync(0xffffffffu, s2, o, 8);
        }
        if (kk == 0) {
            float mu = s * (1.f/256.f);
            cmu[col] = mu;
            crs[col] = rsqrtf(s2*(1.f/256.f) - mu*mu + 1e-5f);
        }
    }
    __syncthreads();

    const float gg = g[tid], bb = bta[tid];
    for (int j = 0; j < 32; j++) {
        int hw = hw0 + j;
        int h = hw / 56, w = hw % 56;
        int hs = h + (56 - SHIFT3); if (hs >= 56) hs -= 56;
        int wsh = w + (56 - SHIFT3); if (wsh >= 56) wsh -= 56;
        int wi = hs / 7, r = hs % 7;
        int wj = wsh / 7, c = wsh % 7;
        int win = ((b << 3) + wi) * 8 + wj;
        int n = r*7 + c;
        ywin[((size_t)win*49 + n)*CH + tid] =
            __float2half_rn((ts[tid*33 + j] - cmu[j]) * crs[j] * gg + bb);
    }
}

// ---------------- fp16 mma GEMM: CTA 128x256, warp 64x64, BK=64, 3-stage ----------------
// Tiles stored [row][64 halfs] = 128B/row; 16B-chunk swizzle: c ^ (row&7).
#define BK 64
#define STAGES 3
#define A_STAGE_B (128*128)
#define B_STAGE_B (256*128)
#define STAGE_B   (A_STAGE_B + B_STAGE_B)
#define SMEM_DYN  (STAGES*STAGE_B)

enum { EPI_BIAS = 0, EPI_PROJLN = 1, EPI_GELU = 2, EPI_RES = 3 };

template<int EPI>
__global__ __launch_bounds__(256) void mma_gemm(
    const __half* __restrict__ A, const __half* __restrict__ BT,
    const float* __restrict__ bias, void* __restrict__ Cp,
    const float* __restrict__ aux,
    const float* __restrict__ gamma, const float* __restrict__ beta2,
    __half* __restrict__ h2out,
    int M, int N, int K)
{
    extern __shared__ char sm[];
    const uint32_t smb = (uint32_t)__cvta_generic_to_shared(sm);

    const int tid  = threadIdx.x;
    const int lane = tid & 31, warp = tid >> 5;
    const int g    = lane >> 2, c4 = lane & 3;
    const int wm0  = (warp >> 2) * 64;
    const int wn0  = (warp & 3) * 64;
    const int m0   = blockIdx.y * 128, n0 = blockIdx.x * 256;

    const int fr  = ((lane >> 3) & 1) * 8 + (lane & 7);
    const int fk  = lane >> 4;

    int arow[4], asw[4], brow[4], bsw[4];
    #pragma unroll
    for (int i = 0; i < 4; i++) {
        int ra = wm0 + i*16 + fr;
        arow[i] = ra*128; asw[i] = ra & 7;
        int rb = wn0 + i*16 + fr;
        brow[i] = rb*128; bsw[i] = rb & 7;
    }

    const int cr = tid >> 3, cc = tid & 7;    // 32 rows x 8 chunks per pass

    float acc[4][8][4];
    #pragma unroll
    for (int i = 0; i < 4; i++)
        #pragma unroll
        for (int j = 0; j < 8; j++)
            #pragma unroll
            for (int k = 0; k < 4; k++) acc[i][j][k] = 0.f;

    auto fill = [&](int t) {
        const int s = t % STAGES;
        const uint32_t ab = smb + (uint32_t)(s*STAGE_B);
        const uint32_t bb = ab + A_STAGE_B;
        const int k0 = t * BK;
        #pragma unroll
        for (int i = 0; i < 4; i++) {
            int rr = cr + 32*i;
            cpasync16(ab + (uint32_t)(rr*128) + (uint32_t)((cc ^ (rr & 7)) << 4),
                      &A[(size_t)(m0 + rr)*K + k0 + cc*8]);
        }
        #pragma unroll
        for (int i = 0; i < 8; i++) {
            int rr = cr + 32*i;
            cpasync16(bb + (uint32_t)(rr*128) + (uint32_t)((cc ^ (rr & 7)) << 4),
                      &BT[(size_t)(n0 + rr)*K + k0 + cc*8]);
        }
    };

    const int nt = K / BK;
    #pragma unroll
    for (int s = 0; s < STAGES-1; s++) {
        fill(s);
        asm volatile("cp.async.commit_group;");
    }

    for (int t = 0; t < nt; t++) {
        asm volatile("cp.async.wait_group %0;" :: "n"(STAGES-2));
        __syncthreads();
        if (t + STAGES - 1 < nt) fill(t + STAGES - 1);
        asm volatile("cp.async.commit_group;");

        const uint32_t ab = smb + (uint32_t)((t % STAGES)*STAGE_B);
        const uint32_t bb = ab + A_STAGE_B;

        #pragma unroll
        for (int kk = 0; kk < 4; kk++) {
            const int kc = kk*2 + fk;
            uint32_t af[4][4], bf[4][4];
            #pragma unroll
            for (int mi = 0; mi < 4; mi++)
                ldsm4(af[mi][0], af[mi][1], af[mi][2], af[mi][3],
                      ab + (uint32_t)arow[mi] + (uint32_t)((kc ^ asw[mi]) << 4));
            #pragma unroll
            for (int np = 0; np < 4; np++)
                ldsm4(bf[np][0], bf[np][1], bf[np][2], bf[np][3],
                      bb + (uint32_t)brow[np] + (uint32_t)((kc ^ bsw[np]) << 4));

            #pragma unroll
            for (int mi = 0; mi < 4; mi++)
                #pragma unroll
                for (int ni = 0; ni < 8; ni++) {
                    const int p = ni >> 1, sb = ni & 1;
                    MMA16816(acc[mi][ni][0], acc[mi][ni][1], acc[mi][ni][2], acc[mi][ni][3],
                             af[mi][0], af[mi][1], af[mi][2], af[mi][3],
                             bf[p][sb], bf[p][2 + sb]);
                }
        }
    }

    // -------- epilogue --------
    if (EPI == EPI_PROJLN) {
        asm volatile("cp.async.wait_group 0;" ::: "memory");
        __syncthreads();
        float* red  = (float*)sm;          // [128][4]
        float* red2 = red + 512;           // [128][4]
        float* smu  = red2 + 512;          // [128]
        float* srs  = smu + 128;           // [128]

        float* C = (float*)Cp;
        float psum[4][2], psum2[4][2];
        #pragma unroll
        for (int mi = 0; mi < 4; mi++) { psum[mi][0]=psum[mi][1]=psum2[mi][0]=psum2[mi][1]=0.f; }

        #pragma unroll
        for (int mi = 0; mi < 4; mi++) {
            #pragma unroll
            for (int h = 0; h < 2; h++) {
                const int m = m0 + wm0 + mi*16 + g + 8*h;
                int win = m / 49, n = m % 49;
                int bq = win >> 6;
                int wr = (win >> 3) & 7;
                int wc = win & 7;
                int rr = n / 7, ccv = n % 7;
                int hh = wr*7 + rr + SHIFT3; if (hh >= 56) hh -= 56;
                int wwv = wc*7 + ccv + SHIFT3; if (wwv >= 56) wwv -= 56;
                int sp = hh*56 + wwv;
                size_t drow = (size_t)bq*HWS + sp;
                #pragma unroll
                for (int ni = 0; ni < 8; ni++) {
                    const int col = wn0 + ni*8 + 2*c4;
                    float v0 = acc[mi][ni][2*h+0] + bias[col] + aux[((size_t)(bq*CH + col    ))*HWS + sp];
                    float v1 = acc[mi][ni][2*h+1] + bias[col+1] + aux[((size_t)(bq*CH + col + 1))*HWS + sp];
                    acc[mi][ni][2*h+0] = v0; acc[mi][ni][2*h+1] = v1;
                    float2 out; out.x = v0; out.y = v1;
                    *reinterpret_cast<float2*>(&C[drow*CH + col]) = out;
                    psum [mi][h] += v0 + v1;
                    psum2[mi][h] += v0*v0 + v1*v1;
                }
            }
        }
        #pragma unroll
        for (int mi = 0; mi < 4; mi++)
            #pragma unroll
            for (int h = 0; h < 2; h++) {
                float s = psum[mi][h], s2 = psum2[mi][h];
                s  += __shfl_xor_sync(0xffffffffu, s, 1);  s  += __shfl_xor_sync(0xffffffffu, s, 2);
                s2 += __shfl_xor_sync(0xffffffffu, s2, 1); s2 += __shfl_xor_sync(0xffffffffu, s2, 2);
                if (c4 == 0) {
                    int rloc = wm0 + mi*16 + g + 8*h;
                    red [rloc*4 + (warp & 3)] = s;
                    red2[rloc*4 + (warp & 3)] = s2;
                }
            }
        __syncthreads();
        if (tid < 128) {
            float s  = red [tid*4] + red [tid*4+1] + red [tid*4+2] + red [tid*4+3];
            float s2 = red2[tid*4] + red2[tid*4+1] + red2[tid*4+2] + red2[tid*4+3];
            float mu = s * (1.f/256.f);
            smu[tid] = mu;
            srs[tid] = rsqrtf(s2*(1.f/256.f) - mu*mu + 1e-5f);
        }
        __syncthreads();
        #pragma unroll
        for (int mi = 0; mi < 4; mi++) {
            #pragma unroll
            for (int h = 0; h < 2; h++) {
                const int rloc = wm0 + mi*16 + g + 8*h;
                const int m = m0 + rloc;
                float mu = smu[rloc], rs = srs[rloc];
                int win = m / 49, n = m % 49;
                int bq = win >> 6;
                int wr = (win >> 3) & 7;
                int wc = win & 7;
                int rr = n / 7, ccv = n % 7;
                int hh = wr*7 + rr + SHIFT3; if (hh >= 56) hh -= 56;
                int wwv = wc*7 + ccv + SHIFT3; if (wwv >= 56) wwv -= 56;
                size_t drow = (size_t)bq*HWS + hh*56 + wwv;
                #pragma unroll
                for (int ni = 0; ni < 8; ni++) {
                    const int col = wn0 + ni*8 + 2*c4;
                    float h0 = (acc[mi][ni][2*h+0] - mu)*rs*gamma[col  ] + beta2[col  ];
                    float h1 = (acc[mi][ni][2*h+1] - mu)*rs*gamma[col+1] + beta2[col+1];
                    *reinterpret_cast<__half2*>(&h2out[drow*CH + col]) = __floats2half2_rn(h0, h1);
                }
            }
        }
        return;
    }

    #pragma unroll
    for (int mi = 0; mi < 4; mi++) {
        #pragma unroll
        for (int h = 0; h < 2; h++) {
            const int m = m0 + wm0 + mi*16 + g + 8*h;
            int bq = 0, sp = 0;
            if (EPI == EPI_RES) { bq = m / HWS; sp = m % HWS; }
            #pragma unroll
            for (int ni = 0; ni < 8; ni++) {
                const int col = n0 + wn0 + ni*8 + 2*c4;
                float v0 = acc[mi][ni][2*h + 0] + bias[col];
                float v1 = acc[mi][ni][2*h + 1] + bias[col + 1];
                if (EPI == EPI_BIAS) {
                    __half2* C = (__half2*)Cp;
                    C[((size_t)m*N + col) >> 1] = __floats2half2_rn(v0, v1);
                } else if (EPI == EPI_GELU) {
                    __half2* C = (__half2*)Cp;
                    float g0 = 0.5f*v0*(1.f + erff(v0*0.70710678118654752f));
                    float g1 = 0.5f*v1*(1.f + erff(v1*0.70710678118654752f));
                    C[((size_t)m*N + col) >> 1] = __floats2half2_rn(g0, g1);
                } else { // EPI_RES
                    float* C = (float*)Cp;
                    float2 a = *reinterpret_cast<const float2*>(&aux[(size_t)m*N + col]);
                    C[((size_t)(bq*CH + col    ))*HWS + sp] = v0 + a.x;
                    C[((size_t)(bq*CH + col + 1))*HWS + sp] = v1 + a.y;
                }
            }
        }
    }
}

// ---------------- kernel 3: tensor-core windowed attention ----------------
#define QK_STRIDE 40
#define VT_STRIDE 72
#define QH_HALFS  (64*QK_STRIDE)
#define VH_HALFS  (32*VT_STRIDE)
#define ATT_SMEM  ((16*QH_HALFS + 8*VH_HALFS)*2)

__global__ __launch_bounds__(256) void attn_kernel(
    const __half* __restrict__ qkv, __half* __restrict__ o)
{
    extern __shared__ __half ash[];
    const int win  = blockIdx.x;
    const int tid  = threadIdx.x;
    const int head = tid >> 5, lane = tid & 31;
    const int g    = lane >> 2, c4 = lane & 3;
    const int fr   = ((lane >> 3) & 1) * 8 + (lane & 7);
    const int fk   = lane >> 4;

    __half* Qb = ash;
    __half* Kb = ash + 8*QH_HALFS;
    __half* Vb = ash + 16*QH_HALFS;

    // zero only V (token padding 49..63 must be exactly 0; Q/K garbage is masked)
    for (int i = tid; i < 8*VH_HALFS/8; i += 256)
        ((uint4*)Vb)[i] = make_uint4(0,0,0,0);
    __syncthreads();

    const __half* src = qkv + (size_t)win*49*QKVN;
    for (int idx = tid; idx < 49*96; idx += 256) {
        int n = idx / 96, ck = idx % 96;
        int sec = ck >> 5;
        int cc  = ck & 31;
        int h   = cc >> 2, dq = (cc & 3)*8;
        uint4 v = *(const uint4*)(src + (size_t)n*QKVN + ck*8);
        if (sec == 0)      *(uint4*)(Qb + h*QH_HALFS + n*QK_STRIDE + dq) = v;
        else if (sec == 1) *(uint4*)(Kb + h*QH_HALFS + n*QK_STRIDE + dq) = v;
        else {
            __half tmp[8]; *(uint4*)tmp = v;
            #pragma unroll
            for (int e = 0; e < 8; e++)
                Vb[h*VH_HALFS + (dq + e)*VT_STRIDE + n] = tmp[e];
        }
    }
    __syncthreads();

    const uint32_t Qsm = (uint32_t)__cvta_generic_to_shared(Qb + head*QH_HALFS) + fr*QK_STRIDE*2;
    const uint32_t Ksm = (uint32_t)__cvta_generic_to_shared(Kb + head*QH_HALFS) + fr*QK_STRIDE*2;
    const uint32_t Vsm = (uint32_t)__cvta_generic_to_shared(Vb + head*VH_HALFS) + fr*VT_STRIDE*2;

    float acc[4][7][4];
    #pragma unroll
    for (int i = 0; i < 4; i++)
        #pragma unroll
        for (int j = 0; j < 7; j++)
            #pragma unroll
            for (int k = 0; k < 4; k++) acc[i][j][k] = 0.f;

    #pragma unroll
    for (int kk = 0; kk < 2; kk++) {
        const int kc = kk*2 + fk;
        uint32_t af[4][4], bf[4][4];
        #pragma unroll
        for (int mi = 0; mi < 4; mi++)
            ldsm4(af[mi][0], af[mi][1], af[mi][2], af[mi][3],
                  Qsm + mi*16*QK_STRIDE*2 + kc*16);
        #pragma unroll
        for (int p = 0; p < 4; p++)
            ldsm4(bf[p][0], bf[p][1], bf[p][2], bf[p][3],
                  Ksm + p*16*QK_STRIDE*2 + kc*16);
        #pragma unroll
        for (int mi = 0; mi < 4; mi++)
            #pragma unroll
            for (int ni = 0; ni < 7; ni++) {
                const int p = ni >> 1, sb = ni & 1;
                MMA16816(acc[mi][ni][0], acc[mi][ni][1], acc[mi][ni][2], acc[mi][ni][3],
                         af[mi][0], af[mi][1], af[mi][2], af[mi][3],
                         bf[p][sb], bf[p][2 + sb]);
            }
    }

    const float scale = 0.17677669529663687f;
    float mx[4][2], sum[4][2];
    #pragma unroll
    for (int mi = 0; mi < 4; mi++) { mx[mi][0] = mx[mi][1] = -1e30f; sum[mi][0] = sum[mi][1] = 0.f; }

    #pragma unroll
    for (int mi = 0; mi < 4; mi++)
        #pragma unroll
        for (int ni = 0; ni < 7; ni++)
            #pragma unroll
            for (int b = 0; b < 2; b++) {
                int j = ni*8 + 2*c4 + b;
                float v0 = acc[mi][ni][b]   * scale;
                float v1 = acc[mi][ni][2+b] * scale;
                if (j >= 49) { v0 = -1e30f; v1 = -1e30f; }
                acc[mi][ni][b] = v0; acc[mi][ni][2+b] = v1;
                mx[mi][0] = fmaxf(mx[mi][0], v0);
                mx[mi][1] = fmaxf(mx[mi][1], v1);
            }
    #pragma unroll
    for (int mi = 0; mi < 4; mi++)
        #pragma unroll
        for (int r = 0; r < 2; r++) {
            float m_ = mx[mi][r];
            m_ = fmaxf(m_, __shfl_xor_sync(0xffffffffu, m_, 1));
            m_ = fmaxf(m_, __shfl_xor_sync(0xffffffffu, m_, 2));
            mx[mi][r] = m_;
        }
    #pragma unroll
    for (int mi = 0; mi < 4; mi++)
        #pragma unroll
        for (int ni = 0; ni < 7; ni++)
            #pragma unroll
            for (int b = 0; b < 2; b++) {
                float e0 = __expf(acc[mi][ni][b]   - mx[mi][0]);
                float e1 = __expf(acc[mi][ni][2+b] - mx[mi][1]);
                acc[mi][ni][b] = e0; acc[mi][ni][2+b] = e1;
                sum[mi][0] += e0; sum[mi][1] += e1;
            }
    #pragma unroll
    for (int mi = 0; mi < 4; mi++)
        #pragma unroll
        for (int r = 0; r < 2; r++) {
            float s_ = sum[mi][r];
            s_ += __shfl_xor_sync(0xffffffffu, s_, 1);
            s_ += __shfl_xor_sync(0xffffffffu, s_, 2);
            sum[mi][r] = 1.f / s_;
        }

    uint32_t ph[4][7][2];
    #pragma unroll
    for (int mi = 0; mi < 4; mi++)
        #pragma unroll
        for (int ni = 0; ni < 7; ni++) {
            __half2 p0 = __floats2half2_rn(acc[mi][ni][0]*sum[mi][0], acc[mi][ni][1]*sum[mi][0]);
            __half2 p1 = __floats2half2_rn(acc[mi][ni][2]*sum[mi][1], acc[mi][ni][3]*sum[mi][1]);
            ph[mi][ni][0] = *reinterpret_cast<uint32_t*>(&p0);
            ph[mi][ni][1] = *reinterpret_cast<uint32_t*>(&p1);
        }

    float oacc[4][4][4];
    #pragma unroll
    for (int i = 0; i < 4; i++)
        #pragma unroll
        for (int j = 0; j < 4; j++)
            #pragma unroll
            for (int k = 0; k < 4; k++) oacc[i][j][k] = 0.f;

    #pragma unroll
    for (int kf = 0; kf < 4; kf++) {
        const int chunk = 2*kf + fk;
        uint32_t bf[2][4];
        #pragma unroll
        for (int p = 0; p < 2; p++)
            ldsm4(bf[p][0], bf[p][1], bf[p][2], bf[p][3],
                  Vsm + p*16*VT_STRIDE*2 + chunk*16);
        #pragma unroll
        for (int mi = 0; mi < 4; mi++) {
            const int n0f = 2*kf, n1f = 2*kf + 1;
            uint32_t a0 = ph[mi][n0f][0], a1 = ph[mi][n0f][1];
            uint32_t a2 = (n1f < 7) ? ph[mi][n1f][0] : 0u;
            uint32_t a3 = (n1f < 7) ? ph[mi][n1f][1] : 0u;
            #pragma unroll
            for (int ni2 = 0; ni2 < 4; ni2++) {
                const int p = ni2 >> 1, sb = ni2 & 1;
                MMA16816(oacc[mi][ni2][0], oacc[mi][ni2][1], oacc[mi][ni2][2], oacc[mi][ni2][3],
                         a0, a1, a2, a3, bf[p][sb], bf[p][2 + sb]);
            }
        }
    }

    #pragma unroll
    for (int mi = 0; mi < 4; mi++) {
        const int i0 = mi*16 + g, i1 = i0 + 8;
        #pragma unroll
        for (int ni2 = 0; ni2 < 4; ni2++) {
            const int col = head*HDIM + ni2*8 + 2*c4;
            if (i0 < 49) {
                __half2 v = __floats2half2_rn(oacc[mi][ni2][0], oacc[mi][ni2][1]);
                *reinterpret_cast<__half2*>(&o[((size_t)win*49 + i0)*CH + col]) = v;
            }
            if (i1 < 49) {
                __half2 v = __floats2half2_rn(oacc[mi][ni2][2], oacc[mi][ni2][3]);
                *reinterpret_cast<__half2*>(&o[((size_t)win*49 + i1)*CH + col]) = v;
            }
        }
    }
}

// ---------------- launch ----------------
extern "C" void kernel_launch(void* const* d_in, const int* in_sizes, int n_in,
                              void* d_out, int out_size)
{
    const float* x      = (const float*)d_in[0];
    const float* n1_g   = (const float*)d_in[1];
    const float* n1_b   = (const float*)d_in[2];
    const float* qkv_w  = (const float*)d_in[3];
    const float* qkv_b  = (const float*)d_in[4];
    const float* proj_w = (const float*)d_in[5];
    const float* proj_b = (const float*)d_in[6];
    const float* n2_g   = (const float*)d_in[7];
    const float* n2_b   = (const float*)d_in[8];
    const float* mlp_w1 = (const float*)d_in[9];
    const float* mlp_b1 = (const float*)d_in[10];
    const float* mlp_w2 = (const float*)d_in[11];
    const float* mlp_b2 = (const float*)d_in[12];

    __half *ywin, *qkvb, *ow, *h2, *hmid;
    float  *x1;
    __half *wqkv, *wproj, *w1, *w2;
    cudaGetSymbolAddress((void**)&ywin,  g_ywin);
    cudaGetSymbolAddress((void**)&qkvb,  g_qkv);
    cudaGetSymbolAddress((void**)&ow,    g_ow);
    cudaGetSymbolAddress((void**)&x1,    g_x1);
    cudaGetSymbolAddress((void**)&h2,    g_h2);
    cudaGetSymbolAddress((void**)&hmid,  g_hmid);
    cudaGetSymbolAddress((void**)&wqkv,  g_wqkv);
    cudaGetSymbolAddress((void**)&wproj, g_wproj);
    cudaGetSymbolAddress((void**)&w1,    g_w1);
    cudaGetSymbolAddress((void**)&w2,    g_w2);

    static bool attr_done = false;
    if (!attr_done) {
        cudaFuncSetAttribute(mma_gemm<EPI_BIAS>,   cudaFuncAttributeMaxDynamicSharedMemorySize, SMEM_DYN);
        cudaFuncSetAttribute(mma_gemm<EPI_PROJLN>, cudaFuncAttributeMaxDynamicSharedMemorySize, SMEM_DYN);
        cudaFuncSetAttribute(mma_gemm<EPI_GELU>,   cudaFuncAttributeMaxDynamicSharedMemorySize, SMEM_DYN);
        cudaFuncSetAttribute(mma_gemm<EPI_RES>,    cudaFuncAttributeMaxDynamicSharedMemorySize, SMEM_DYN);
        cudaFuncSetAttribute(attn_kernel,          cudaFuncAttributeMaxDynamicSharedMemorySize, ATT_SMEM);
        attr_done = true;
    }

    // 0) all weights: transpose + fp16 round -> [N][K]  (one launch)
    transpose_round_all<<<768, 256>>>(qkv_w, wqkv, proj_w, wproj, mlp_w1, w1, mlp_w2, w2);

    // 1) LN1 + shift + window partition
    ln1_kernel<<<BATCH*98, 256>>>(x, n1_g, n1_b, ywin);

    // 2) qkv = ywin @ qkv_w + qkv_b
    mma_gemm<EPI_BIAS><<<dim3(QKVN/256, TOK/128), 256, SMEM_DYN>>>(
        ywin, wqkv, qkv_b, qkvb, nullptr, nullptr, nullptr, nullptr, TOK, QKVN, CH);

    // 3) tensor-core windowed attention
    attn_kernel<<<2048, 256, ATT_SMEM>>>(qkvb, ow);

    // 4) x1 = shortcut(x) + proj(ow); h2 = LN2(x1)   (fused)
    mma_gemm<EPI_PROJLN><<<dim3(CH/256, TOK/128), 256, SMEM_DYN>>>(
        ow, wproj, proj_b, x1, x, n2_g, n2_b, h2, TOK, CH, CH);

    // 5) hmid = gelu(h2 @ mlp_w1 + mlp_b1)
    mma_gemm<EPI_GELU><<<dim3(HIDDEN/256, TOK/128), 256, SMEM_DYN>>>(
        h2, w1, mlp_b1, hmid, nullptr, nullptr, nullptr, nullptr, TOK, HIDDEN, CH);

    // 6) out(NCHW) = x1 + hmid @ mlp_w2 + mlp_b2   (fused transpose)
    mma_gemm<EPI_RES><<<dim3(CH/256, TOK/128), 256, SMEM_DYN>>>(
        hmid, w2, mlp_b2, (float*)d_out, x1, nullptr, nullptr, nullptr, TOK, CH, HIDDEN);
}

// round 9
// speedup vs baseline: 4.6021x; 1.0849x over previous
#include <cuda_runtime.h>
#include <cuda_fp16.h>
#include <math.h>
#include <stdint.h>

// ---------------- problem constants ----------------
#define BATCH 32
#define CH    256
#define HWS   3136
#define TOK   100352
#define SHIFT3 3
#define HEADS 8
#define HDIM  32
#define HIDDEN 1024
#define QKVN  768

// ---------------- scratch ----------------
__device__ __half g_ywin [(size_t)TOK*CH];
__device__ __half g_qkv  [(size_t)TOK*QKVN];
__device__ __half g_ow   [(size_t)TOK*CH];
__device__ float  g_x1   [(size_t)TOK*CH];
__device__ __half g_h2   [(size_t)TOK*CH];
__device__ __half g_hmid [(size_t)TOK*HIDDEN];
// fp16, TRANSPOSED weight copies: [N][K]
__device__ __half g_wqkv [QKVN*CH];
__device__ __half g_wproj[CH*CH];
__device__ __half g_w1   [HIDDEN*CH];
__device__ __half g_w2   [CH*HIDDEN];

__device__ __forceinline__ void cpasync16(uint32_t dst, const void* src) {
    asm volatile("cp.async.cg.shared.global [%0], [%1], 16;" :: "r"(dst), "l"(src));
}

__device__ __forceinline__ void ldsm4(uint32_t& r0, uint32_t& r1, uint32_t& r2, uint32_t& r3,
                                      uint32_t addr) {
    asm volatile("ldmatrix.sync.aligned.m8n8.x4.shared.b16 {%0,%1,%2,%3}, [%4];"
                 : "=r"(r0), "=r"(r1), "=r"(r2), "=r"(r3) : "r"(addr));
}

__device__ __forceinline__ void ldsm4t(uint32_t& r0, uint32_t& r1, uint32_t& r2, uint32_t& r3,
                                       uint32_t addr) {
    asm volatile("ldmatrix.sync.aligned.m8n8.x4.trans.shared.b16 {%0,%1,%2,%3}, [%4];"
                 : "=r"(r0), "=r"(r1), "=r"(r2), "=r"(r3) : "r"(addr));
}

#define MMA16816(d0,d1,d2,d3,a0,a1,a2,a3,b0,b1) \
    asm volatile( \
        "mma.sync.aligned.m16n8k16.row.col.f32.f16.f16.f32 " \
        "{%0,%1,%2,%3}, {%4,%5,%6,%7}, {%8,%9}, {%0,%1,%2,%3};" \
        : "+f"(d0), "+f"(d1), "+f"(d2), "+f"(d3) \
        : "r"(a0), "r"(a1), "r"(a2), "r"(a3), "r"(b0), "r"(b1))

// ---------------- prep: ALL weights transpose + fp16 round, one launch ----------------
__global__ __launch_bounds__(256) void transpose_round_all(
    const float* __restrict__ w0, __half* __restrict__ o0,
    const float* __restrict__ w1_, __half* __restrict__ o1,
    const float* __restrict__ w2_, __half* __restrict__ o2,
    const float* __restrict__ w3_, __half* __restrict__ o3)
{
    __shared__ float t[32][33];
    int blk = blockIdx.x;
    const float* w; __half* wt; int K, N, nb;
    if (blk < 192)      { w = w0;  wt = o0; K = CH;     N = QKVN;   nb = QKVN/32; }
    else if (blk < 256) { blk -= 192; w = w1_; wt = o1; K = CH;     N = CH;     nb = CH/32; }
    else if (blk < 512) { blk -= 256; w = w2_; wt = o2; K = CH;     N = HIDDEN; nb = HIDDEN/32; }
    else                { blk -= 512; w = w3_; wt = o3; K = HIDDEN; N = CH;     nb = CH/32; }
    const int k0 = (blk / nb) * 32, n0 = (blk % nb) * 32;
    const int x = threadIdx.x & 31, y = threadIdx.x >> 5;
    for (int yy = y; yy < 32; yy += 8)
        t[yy][x] = w[(size_t)(k0 + yy)*N + n0 + x];
    __syncthreads();
    for (int yy = y; yy < 32; yy += 8)
        wt[(size_t)(n0 + yy)*K + k0 + x] = __float2half_rn(t[x][yy]);
}

// ---------------- kernel 1: LN1 + shift + window partition ----------------
__global__ __launch_bounds__(256) void ln1_kernel(
    const float* __restrict__ x, const float* __restrict__ g, const float* __restrict__ bta,
    __half* __restrict__ ywin)
{
    __shared__ float ts[256*33];
    __shared__ float cmu[32], crs[32];
    const int blk = blockIdx.x;
    const int b   = blk / 98;
    const int hw0 = (blk % 98) * 32;
    const int tid = threadIdx.x;
    const float* xb = x + (size_t)b*CH*HWS;

    for (int idx = tid; idx < 256*32; idx += 256) {
        int ch = idx >> 5, j = idx & 31;
        ts[ch*33 + j] = xb[(size_t)ch*HWS + hw0 + j];
    }
    __syncthreads();

    {
        int col = tid >> 3, kk = tid & 7;
        float s = 0.f, s2 = 0.f;
        for (int ch = kk; ch < 256; ch += 8) {
            float v = ts[ch*33 + col];
            s += v; s2 += v*v;
        }
        #pragma unroll
        for (int o = 4; o; o >>= 1) {
            s  += __shfl_down_sync(0xffffffffu, s,  o, 8);
            s2 += __shfl_down_sync(0xffffffffu, s2, o, 8);
        }
        if (kk == 0) {
            float mu = s * (1.f/256.f);
            cmu[col] = mu;
            crs[col] = rsqrtf(s2*(1.f/256.f) - mu*mu + 1e-5f);
        }
    }
    __syncthreads();

    const float gg = g[tid], bb = bta[tid];
    for (int j = 0; j < 32; j++) {
        int hw = hw0 + j;
        int h = hw / 56, w = hw % 56;
        int hs = h + (56 - SHIFT3); if (hs >= 56) hs -= 56;
        int wsh = w + (56 - SHIFT3); if (wsh >= 56) wsh -= 56;
        int wi = hs / 7, r = hs % 7;
        int wj = wsh / 7, c = wsh % 7;
        int win = ((b << 3) + wi) * 8 + wj;
        int n = r*7 + c;
        ywin[((size_t)win*49 + n)*CH + tid] =
            __float2half_rn((ts[tid*33 + j] - cmu[j]) * crs[j] * gg + bb);
    }
}

// ---------------- fp16 mma GEMM: CTA 128x256, warp 64x64, BK=64, 3-stage ----------------
#define BK 64
#define STAGES 3
#define A_STAGE_B (128*128)
#define B_STAGE_B (256*128)
#define STAGE_B   (A_STAGE_B + B_STAGE_B)
#define SMEM_DYN  (STAGES*STAGE_B)

enum { EPI_BIAS = 0, EPI_PROJLN = 1, EPI_GELU = 2, EPI_RES = 3 };

template<int EPI>
__global__ __launch_bounds__(256) void mma_gemm(
    const __half* __restrict__ A, const __half* __restrict__ BT,
    const float* __restrict__ bias, void* __restrict__ Cp,
    const float* __restrict__ aux,
    const float* __restrict__ gamma, const float* __restrict__ beta2,
    __half* __restrict__ h2out,
    int M, int N, int K)
{
    extern __shared__ char sm[];
    const uint32_t smb = (uint32_t)__cvta_generic_to_shared(sm);

    const int tid  = threadIdx.x;
    const int lane = tid & 31, warp = tid >> 5;
    const int g    = lane >> 2, c4 = lane & 3;
    const int wm0  = (warp >> 2) * 64;
    const int wn0  = (warp & 3) * 64;
    const int m0   = blockIdx.y * 128, n0 = blockIdx.x * 256;

    const int fr  = ((lane >> 3) & 1) * 8 + (lane & 7);
    const int fk  = lane >> 4;

    int arow[4], asw[4], brow[4], bsw[4];
    #pragma unroll
    for (int i = 0; i < 4; i++) {
        int ra = wm0 + i*16 + fr;
        arow[i] = ra*128; asw[i] = ra & 7;
        int rb = wn0 + i*16 + fr;
        brow[i] = rb*128; bsw[i] = rb & 7;
    }

    const int cr = tid >> 3, cc = tid & 7;

    float acc[4][8][4];
    #pragma unroll
    for (int i = 0; i < 4; i++)
        #pragma unroll
        for (int j = 0; j < 8; j++)
            #pragma unroll
            for (int k = 0; k < 4; k++) acc[i][j][k] = 0.f;

    auto fill = [&](int t) {
        const int s = t % STAGES;
        const uint32_t ab = smb + (uint32_t)(s*STAGE_B);
        const uint32_t bb = ab + A_STAGE_B;
        const int k0 = t * BK;
        #pragma unroll
        for (int i = 0; i < 4; i++) {
            int rr = cr + 32*i;
            cpasync16(ab + (uint32_t)(rr*128) + (uint32_t)((cc ^ (rr & 7)) << 4),
                      &A[(size_t)(m0 + rr)*K + k0 + cc*8]);
        }
        #pragma unroll
        for (int i = 0; i < 8; i++) {
            int rr = cr + 32*i;
            cpasync16(bb + (uint32_t)(rr*128) + (uint32_t)((cc ^ (rr & 7)) << 4),
                      &BT[(size_t)(n0 + rr)*K + k0 + cc*8]);
        }
    };

    const int nt = K / BK;
    #pragma unroll
    for (int s = 0; s < STAGES-1; s++) {
        fill(s);
        asm volatile("cp.async.commit_group;");
    }

    for (int t = 0; t < nt; t++) {
        asm volatile("cp.async.wait_group %0;" :: "n"(STAGES-2));
        __syncthreads();
        if (t + STAGES - 1 < nt) fill(t + STAGES - 1);
        asm volatile("cp.async.commit_group;");

        const uint32_t ab = smb + (uint32_t)((t % STAGES)*STAGE_B);
        const uint32_t bb = ab + A_STAGE_B;

        #pragma unroll
        for (int kk = 0; kk < 4; kk++) {
            const int kc = kk*2 + fk;
            uint32_t af[4][4], bf[4][4];
            #pragma unroll
            for (int mi = 0; mi < 4; mi++)
                ldsm4(af[mi][0], af[mi][1], af[mi][2], af[mi][3],
                      ab + (uint32_t)arow[mi] + (uint32_t)((kc ^ asw[mi]) << 4));
            #pragma unroll
            for (int np = 0; np < 4; np++)
                ldsm4(bf[np][0], bf[np][1], bf[np][2], bf[np][3],
                      bb + (uint32_t)brow[np] + (uint32_t)((kc ^ bsw[np]) << 4));

            #pragma unroll
            for (int mi = 0; mi < 4; mi++)
                #pragma unroll
                for (int ni = 0; ni < 8; ni++) {
                    const int p = ni >> 1, sb = ni & 1;
                    MMA16816(acc[mi][ni][0], acc[mi][ni][1], acc[mi][ni][2], acc[mi][ni][3],
                             af[mi][0], af[mi][1], af[mi][2], af[mi][3],
                             bf[p][sb], bf[p][2 + sb]);
                }
        }
    }

    // -------- epilogue --------
    if (EPI == EPI_PROJLN) {
        asm volatile("cp.async.wait_group 0;" ::: "memory");
        __syncthreads();
        float* red  = (float*)sm;
        float* red2 = red + 512;
        float* smu  = red2 + 512;
        float* srs  = smu + 128;

        float* C = (float*)Cp;
        float psum[4][2], psum2[4][2];
        #pragma unroll
        for (int mi = 0; mi < 4; mi++) { psum[mi][0]=psum[mi][1]=psum2[mi][0]=psum2[mi][1]=0.f; }

        #pragma unroll
        for (int mi = 0; mi < 4; mi++) {
            #pragma unroll
            for (int h = 0; h < 2; h++) {
                const int m = m0 + wm0 + mi*16 + g + 8*h;
                int win = m / 49, n = m % 49;
                int bq = win >> 6;
                int wr = (win >> 3) & 7;
                int wc = win & 7;
                int rr = n / 7, ccv = n % 7;
                int hh = wr*7 + rr + SHIFT3; if (hh >= 56) hh -= 56;
                int wwv = wc*7 + ccv + SHIFT3; if (wwv >= 56) wwv -= 56;
                int sp = hh*56 + wwv;
                size_t drow = (size_t)bq*HWS + sp;
                #pragma unroll
                for (int ni = 0; ni < 8; ni++) {
                    const int col = wn0 + ni*8 + 2*c4;
                    float v0 = acc[mi][ni][2*h+0] + bias[col] + aux[((size_t)(bq*CH + col    ))*HWS + sp];
                    float v1 = acc[mi][ni][2*h+1] + bias[col+1] + aux[((size_t)(bq*CH + col + 1))*HWS + sp];
                    acc[mi][ni][2*h+0] = v0; acc[mi][ni][2*h+1] = v1;
                    float2 out; out.x = v0; out.y = v1;
                    *reinterpret_cast<float2*>(&C[drow*CH + col]) = out;
                    psum [mi][h] += v0 + v1;
                    psum2[mi][h] += v0*v0 + v1*v1;
                }
            }
        }
        #pragma unroll
        for (int mi = 0; mi < 4; mi++)
            #pragma unroll
            for (int h = 0; h < 2; h++) {
                float s = psum[mi][h], s2 = psum2[mi][h];
                s  += __shfl_xor_sync(0xffffffffu, s, 1);  s  += __shfl_xor_sync(0xffffffffu, s, 2);
                s2 += __shfl_xor_sync(0xffffffffu, s2, 1); s2 += __shfl_xor_sync(0xffffffffu, s2, 2);
                if (c4 == 0) {
                    int rloc = wm0 + mi*16 + g + 8*h;
                    red [rloc*4 + (warp & 3)] = s;
                    red2[rloc*4 + (warp & 3)] = s2;
                }
            }
        __syncthreads();
        if (tid < 128) {
            float s  = red [tid*4] + red [tid*4+1] + red [tid*4+2] + red [tid*4+3];
            float s2 = red2[tid*4] + red2[tid*4+1] + red2[tid*4+2] + red2[tid*4+3];
            float mu = s * (1.f/256.f);
            smu[tid] = mu;
            srs[tid] = rsqrtf(s2*(1.f/256.f) - mu*mu + 1e-5f);
        }
        __syncthreads();
        #pragma unroll
        for (int mi = 0; mi < 4; mi++) {
            #pragma unroll
            for (int h = 0; h < 2; h++) {
                const int rloc = wm0 + mi*16 + g + 8*h;
                const int m = m0 + rloc;
                float mu = smu[rloc], rs = srs[rloc];
                int win = m / 49, n = m % 49;
                int bq = win >> 6;
                int wr = (win >> 3) & 7;
                int wc = win & 7;
                int rr = n / 7, ccv = n % 7;
                int hh = wr*7 + rr + SHIFT3; if (hh >= 56) hh -= 56;
                int wwv = wc*7 + ccv + SHIFT3; if (wwv >= 56) wwv -= 56;
                size_t drow = (size_t)bq*HWS + hh*56 + wwv;
                #pragma unroll
                for (int ni = 0; ni < 8; ni++) {
                    const int col = wn0 + ni*8 + 2*c4;
                    float h0 = (acc[mi][ni][2*h+0] - mu)*rs*gamma[col  ] + beta2[col  ];
                    float h1 = (acc[mi][ni][2*h+1] - mu)*rs*gamma[col+1] + beta2[col+1];
                    *reinterpret_cast<__half2*>(&h2out[drow*CH + col]) = __floats2half2_rn(h0, h1);
                }
            }
        }
        return;
    }

    #pragma unroll
    for (int mi = 0; mi < 4; mi++) {
        #pragma unroll
        for (int h = 0; h < 2; h++) {
            const int m = m0 + wm0 + mi*16 + g + 8*h;
            int bq = 0, sp = 0;
            if (EPI == EPI_RES) { bq = m / HWS; sp = m % HWS; }
            #pragma unroll
            for (int ni = 0; ni < 8; ni++) {
                const int col = n0 + wn0 + ni*8 + 2*c4;
                float v0 = acc[mi][ni][2*h + 0] + bias[col];
                float v1 = acc[mi][ni][2*h + 1] + bias[col + 1];
                if (EPI == EPI_BIAS) {
                    __half2* C = (__half2*)Cp;
                    C[((size_t)m*N + col) >> 1] = __floats2half2_rn(v0, v1);
                } else if (EPI == EPI_GELU) {
                    __half2* C = (__half2*)Cp;
                    float g0 = 0.5f*v0*(1.f + erff(v0*0.70710678118654752f));
                    float g1 = 0.5f*v1*(1.f + erff(v1*0.70710678118654752f));
                    C[((size_t)m*N + col) >> 1] = __floats2half2_rn(g0, g1);
                } else { // EPI_RES
                    float* C = (float*)Cp;
                    float2 a = *reinterpret_cast<const float2*>(&aux[(size_t)m*N + col]);
                    C[((size_t)(bq*CH + col    ))*HWS + sp] = v0 + a.x;
                    C[((size_t)(bq*CH + col + 1))*HWS + sp] = v1 + a.y;
                }
            }
        }
    }
}

// ---------------- kernel 3: tensor-core windowed attention (512 thr, 2 warps/head) ----------------
// Q/K/V all row-major per head: 64 rows x 40 halfs (80B stride), tokens 0..48 valid.
#define T_STRIDE 40
#define REG_HALFS (64*T_STRIDE)   // 2560
#define ATT_SMEM  (24*REG_HALFS*2)  // 122880 B

__global__ __launch_bounds__(512) void attn_kernel(
    const __half* __restrict__ qkv, __half* __restrict__ o)
{
    extern __shared__ __half ash[];
    const int win  = blockIdx.x;
    const int tid  = threadIdx.x;
    const int warp = tid >> 5, lane = tid & 31;
    const int head = warp >> 1, half = warp & 1;
    const int g    = lane >> 2, c4 = lane & 3;
    const int fr   = ((lane >> 3) & 1) * 8 + (lane & 7);
    const int fk   = lane >> 4;

    __half* Qb = ash;
    __half* Kb = ash + 8*REG_HALFS;
    __half* Vb = ash + 16*REG_HALFS;

    // zero V token-pad rows 49..63 (P=0 there; prevents NaN/Inf garbage)
    for (int i = tid; i < 600; i += 512) {
        int h = i / 75, rem = i % 75;
        int row = 49 + rem / 5, q = rem % 5;
        *(uint4*)(Vb + h*REG_HALFS + row*T_STRIDE + q*8) = make_uint4(0,0,0,0);
    }
    __syncthreads();

    // uniform vectorized load: 49 tokens x 96 16B-chunks
    const __half* src = qkv + (size_t)win*49*QKVN;
    for (int idx = tid; idx < 49*96; idx += 512) {
        int n = idx / 96, ck = idx % 96;
        int sec = ck >> 5;
        int cc  = ck & 31;
        int h   = cc >> 2, dq = (cc & 3)*8;
        uint4 v = *(const uint4*)(src + (size_t)n*QKVN + ck*8);
        __half* base = (sec == 0) ? Qb : (sec == 1) ? Kb : Vb;
        *(uint4*)(base + h*REG_HALFS + n*T_STRIDE + dq) = v;
    }
    __syncthreads();

    const uint32_t Qsm = (uint32_t)__cvta_generic_to_shared(Qb + head*REG_HALFS)
                       + (half*32 + fr)*T_STRIDE*2;
    const uint32_t Ksm = (uint32_t)__cvta_generic_to_shared(Kb + head*REG_HALFS)
                       + fr*T_STRIDE*2;
    const uint32_t Vsm = (uint32_t)__cvta_generic_to_shared(Vb + head*REG_HALFS)
                       + fr*T_STRIDE*2;

    // ---- S = Q K^T (32 q-rows per warp) ----
    float acc[2][7][4];
    #pragma unroll
    for (int i = 0; i < 2; i++)
        #pragma unroll
        for (int j = 0; j < 7; j++)
            #pragma unroll
            for (int k = 0; k < 4; k++) acc[i][j][k] = 0.f;

    #pragma unroll
    for (int kk = 0; kk < 2; kk++) {
        const int kc = kk*2 + fk;
        uint32_t af[2][4], bf[4][4];
        #pragma unroll
        for (int mi = 0; mi < 2; mi++)
            ldsm4(af[mi][0], af[mi][1], af[mi][2], af[mi][3],
                  Qsm + mi*16*T_STRIDE*2 + kc*16);
        #pragma unroll
        for (int p = 0; p < 4; p++)
            ldsm4(bf[p][0], bf[p][1], bf[p][2], bf[p][3],
                  Ksm + p*16*T_STRIDE*2 + kc*16);
        #pragma unroll
        for (int mi = 0; mi < 2; mi++)
            #pragma unroll
            for (int ni = 0; ni < 7; ni++) {
                const int p = ni >> 1, sb = ni & 1;
                MMA16816(acc[mi][ni][0], acc[mi][ni][1], acc[mi][ni][2], acc[mi][ni][3],
                         af[mi][0], af[mi][1], af[mi][2], af[mi][3],
                         bf[p][sb], bf[p][2 + sb]);
            }
    }

    // ---- softmax (register) ----
    const float scale = 0.17677669529663687f;
    float mx[2][2], sum[2][2];
    #pragma unroll
    for (int mi = 0; mi < 2; mi++) { mx[mi][0] = mx[mi][1] = -1e30f; sum[mi][0] = sum[mi][1] = 0.f; }

    #pragma unroll
    for (int mi = 0; mi < 2; mi++)
        #pragma unroll
        for (int ni = 0; ni < 7; ni++)
            #pragma unroll
            for (int b = 0; b < 2; b++) {
                int j = ni*8 + 2*c4 + b;
                float v0 = acc[mi][ni][b]   * scale;
                float v1 = acc[mi][ni][2+b] * scale;
                if (j >= 49) { v0 = -1e30f; v1 = -1e30f; }
                acc[mi][ni][b] = v0; acc[mi][ni][2+b] = v1;
                mx[mi][0] = fmaxf(mx[mi][0], v0);
                mx[mi][1] = fmaxf(mx[mi][1], v1);
            }
    #pragma unroll
    for (int mi = 0; mi < 2; mi++)
        #pragma unroll
        for (int r = 0; r < 2; r++) {
            float m_ = mx[mi][r];
            m_ = fmaxf(m_, __shfl_xor_sync(0xffffffffu, m_, 1));
            m_ = fmaxf(m_, __shfl_xor_sync(0xffffffffu, m_, 2));
            mx[mi][r] = m_;
        }
    #pragma unroll
    for (int mi = 0; mi < 2; mi++)
        #pragma unroll
        for (int ni = 0; ni < 7; ni++)
            #pragma unroll
            for (int b = 0; b < 2; b++) {
                float e0 = __expf(acc[mi][ni][b]   - mx[mi][0]);
                float e1 = __expf(acc[mi][ni][2+b] - mx[mi][1]);
                acc[mi][ni][b] = e0; acc[mi][ni][2+b] = e1;
                sum[mi][0] += e0; sum[mi][1] += e1;
            }
    #pragma unroll
    for (int mi = 0; mi < 2; mi++)
        #pragma unroll
        for (int r = 0; r < 2; r++) {
            float s_ = sum[mi][r];
            s_ += __shfl_xor_sync(0xffffffffu, s_, 1);
            s_ += __shfl_xor_sync(0xffffffffu, s_, 2);
            sum[mi][r] = 1.f / s_;
        }

    uint32_t ph[2][7][2];
    #pragma unroll
    for (int mi = 0; mi < 2; mi++)
        #pragma unroll
        for (int ni = 0; ni < 7; ni++) {
            __half2 p0 = __floats2half2_rn(acc[mi][ni][0]*sum[mi][0], acc[mi][ni][1]*sum[mi][0]);
            __half2 p1 = __floats2half2_rn(acc[mi][ni][2]*sum[mi][1], acc[mi][ni][3]*sum[mi][1]);
            ph[mi][ni][0] = *reinterpret_cast<uint32_t*>(&p0);
            ph[mi][ni][1] = *reinterpret_cast<uint32_t*>(&p1);
        }

    // ---- O = P V  (V row-major, ldmatrix.trans B operand) ----
    float oacc[2][4][4];
    #pragma unroll
    for (int i = 0; i < 2; i++)
        #pragma unroll
        for (int j = 0; j < 4; j++)
            #pragma unroll
            for (int k = 0; k < 4; k++) oacc[i][j][k] = 0.f;

    #pragma unroll
    for (int kf = 0; kf < 4; kf++) {
        uint32_t bf[2][4];
        #pragma unroll
        for (int cp = 0; cp < 2; cp++)
            ldsm4t(bf[cp][0], bf[cp][1], bf[cp][2], bf[cp][3],
                   Vsm + kf*16*T_STRIDE*2 + (2*cp + fk)*16);
        #pragma unroll
        for (int mi = 0; mi < 2; mi++) {
            const int n0f = 2*kf, n1f = 2*kf + 1;
            uint32_t a0 = ph[mi][n0f][0], a1 = ph[mi][n0f][1];
            uint32_t a2 = (n1f < 7) ? ph[mi][n1f][0] : 0u;
            uint32_t a3 = (n1f < 7) ? ph[mi][n1f][1] : 0u;
            #pragma unroll
            for (int ni2 = 0; ni2 < 4; ni2++) {
                const int cp = ni2 >> 1, q = ni2 & 1;
                MMA16816(oacc[mi][ni2][0], oacc[mi][ni2][1], oacc[mi][ni2][2], oacc[mi][ni2][3],
                         a0, a1, a2, a3, bf[cp][2*q], bf[cp][2*q + 1]);
            }
        }
    }

    // ---- store O ----
    #pragma unroll
    for (int mi = 0; mi < 2; mi++) {
        const int i0 = half*32 + mi*16 + g, i1 = i0 + 8;
        #pragma unroll
        for (int ni2 = 0; ni2 < 4; ni2++) {
            const int col = head*HDIM + ni2*8 + 2*c4;
            if (i0 < 49) {
                __half2 v = __floats2half2_rn(oacc[mi][ni2][0], oacc[mi][ni2][1]);
                *reinterpret_cast<__half2*>(&o[((size_t)win*49 + i0)*CH + col]) = v;
            }
            if (i1 < 49) {
                __half2 v = __floats2half2_rn(oacc[mi][ni2][2], oacc[mi][ni2][3]);
                *reinterpret_cast<__half2*>(&o[((size_t)win*49 + i1)*CH + col]) = v;
            }
        }
    }
}

// ---------------- launch ----------------
extern "C" void kernel_launch(void* const* d_in, const int* in_sizes, int n_in,
                              void* d_out, int out_size)
{
    const float* x      = (const float*)d_in[0];
    const float* n1_g   = (const float*)d_in[1];
    const float* n1_b   = (const float*)d_in[2];
    const float* qkv_w  = (const float*)d_in[3];
    const float* qkv_b  = (const float*)d_in[4];
    const float* proj_w = (const float*)d_in[5];
    const float* proj_b = (const float*)d_in[6];
    const float* n2_g   = (const float*)d_in[7];
    const float* n2_b   = (const float*)d_in[8];
    const float* mlp_w1 = (const float*)d_in[9];
    const float* mlp_b1 = (const float*)d_in[10];
    const float* mlp_w2 = (const float*)d_in[11];
    const float* mlp_b2 = (const float*)d_in[12];

    __half *ywin, *qkvb, *ow, *h2, *hmid;
    float  *x1;
    __half *wqkv, *wproj, *w1, *w2;
    cudaGetSymbolAddress((void**)&ywin,  g_ywin);
    cudaGetSymbolAddress((void**)&qkvb,  g_qkv);
    cudaGetSymbolAddress((void**)&ow,    g_ow);
    cudaGetSymbolAddress((void**)&x1,    g_x1);
    cudaGetSymbolAddress((void**)&h2,    g_h2);
    cudaGetSymbolAddress((void**)&hmid,  g_hmid);
    cudaGetSymbolAddress((void**)&wqkv,  g_wqkv);
    cudaGetSymbolAddress((void**)&wproj, g_wproj);
    cudaGetSymbolAddress((void**)&w1,    g_w1);
    cudaGetSymbolAddress((void**)&w2,    g_w2);

    static bool attr_done = false;
    if (!attr_done) {
        cudaFuncSetAttribute(mma_gemm<EPI_BIAS>,   cudaFuncAttributeMaxDynamicSharedMemorySize, SMEM_DYN);
        cudaFuncSetAttribute(mma_gemm<EPI_PROJLN>, cudaFuncAttributeMaxDynamicSharedMemorySize, SMEM_DYN);
        cudaFuncSetAttribute(mma_gemm<EPI_GELU>,   cudaFuncAttributeMaxDynamicSharedMemorySize, SMEM_DYN);
        cudaFuncSetAttribute(mma_gemm<EPI_RES>,    cudaFuncAttributeMaxDynamicSharedMemorySize, SMEM_DYN);
        cudaFuncSetAttribute(attn_kernel,          cudaFuncAttributeMaxDynamicSharedMemorySize, ATT_SMEM);
        attr_done = true;
    }

    // 0) all weights: transpose + fp16 round -> [N][K]
    transpose_round_all<<<768, 256>>>(qkv_w, wqkv, proj_w, wproj, mlp_w1, w1, mlp_w2, w2);

    // 1) LN1 + shift + window partition
    ln1_kernel<<<BATCH*98, 256>>>(x, n1_g, n1_b, ywin);

    // 2) qkv = ywin @ qkv_w + qkv_b
    mma_gemm<EPI_BIAS><<<dim3(QKVN/256, TOK/128), 256, SMEM_DYN>>>(
        ywin, wqkv, qkv_b, qkvb, nullptr, nullptr, nullptr, nullptr, TOK, QKVN, CH);

    // 3) tensor-core windowed attention
    attn_kernel<<<2048, 512, ATT_SMEM>>>(qkvb, ow);

    // 4) x1 = shortcut(x) + proj(ow); h2 = LN2(x1)   (fused)
    mma_gemm<EPI_PROJLN><<<dim3(CH/256, TOK/128), 256, SMEM_DYN>>>(
        ow, wproj, proj_b, x1, x, n2_g, n2_b, h2, TOK, CH, CH);

    // 5) hmid = gelu(h2 @ mlp_w1 + mlp_b1)
    mma_gemm<EPI_GELU><<<dim3(HIDDEN/256, TOK/128), 256, SMEM_DYN>>>(
        h2, w1, mlp_b1, hmid, nullptr, nullptr, nullptr, nullptr, TOK, HIDDEN, CH);

    // 6) out(NCHW) = x1 + hmid @ mlp_w2 + mlp_b2   (fused transpose)
    mma_gemm<EPI_RES><<<dim3(CH/256, TOK/128), 256, SMEM_DYN>>>(
        hmid, w2, mlp_b2, (float*)d_out, x1, nullptr, nullptr, nullptr, TOK, CH, HIDDEN);
}